// round 4
// baseline (speedup 1.0000x reference)
#include <cuda_runtime.h>
#include <cuda_bf16.h>
#include <cstdint>
#include <math.h>

// Problem constants (fixed by reference setup_inputs)
#define BB 2
#define NN 20000
#define DD 256
#define HH 8
#define DH 32
#define DEG 8
#define ROWS (BB*NN)          // 40000
#define PADROWS 40064         // padded to multiple of 128 for unguarded tile loads
#define LN_EPS 1e-3f
#define INV_SQRT_DH 0.17677669529663687f  // 1/sqrt(32)

// ---------------- scratch (device globals; no allocations allowed) ----------------
__device__ __nv_bfloat16 g_xnh[(size_t)PADROWS * DD];   // LN1 out hi
__device__ __nv_bfloat16 g_xnl[(size_t)PADROWS * DD];   // LN1 out lo
__device__ __nv_bfloat16 g_th [(size_t)PADROWS * DD];   // LN2 out hi
__device__ __nv_bfloat16 g_tl [(size_t)PADROWS * DD];   // LN2 out lo
__device__ float g_qkv[(size_t)ROWS * 3 * DD];          // q|k|v per row (fp32)
__device__ float g_concat[(size_t)ROWS * DD];           // xn + attn (fp32)
__device__ float g_bias[768];                           // packed [bq|bk|bv]
__device__ __nv_bfloat16 g_wqkvTh[768 * 256];           // W^T hi  [n][k]
__device__ __nv_bfloat16 g_wqkvTl[768 * 256];           // W^T lo
__device__ __nv_bfloat16 g_woTh[256 * 256];             // wo^T hi
__device__ __nv_bfloat16 g_woTl[256 * 256];             // wo^T lo

// ---------------- PTX helpers (sm_80-era: valid on base sm_103 target) ----------------
__device__ __forceinline__ void cp_async16(uint32_t dst, const void* src) {
    asm volatile("cp.async.cg.shared.global [%0], [%1], 16;" :: "r"(dst), "l"(src));
}
#define CP_COMMIT() asm volatile("cp.async.commit_group;" ::: "memory")
#define CP_WAIT(n)  asm volatile("cp.async.wait_group %0;" :: "n"(n) : "memory")

__device__ __forceinline__ uint32_t smem_to_u32(const void* p) {
    uint32_t a;
    asm("{ .reg .u64 t; cvta.to.shared.u64 t, %1; cvt.u32.u64 %0, t; }" : "=r"(a) : "l"(p));
    return a;
}
__device__ __forceinline__ void ldsm4(uint32_t* r, uint32_t addr) {
    asm volatile("ldmatrix.sync.aligned.m8n8.x4.shared.b16 {%0,%1,%2,%3}, [%4];"
        : "=r"(r[0]), "=r"(r[1]), "=r"(r[2]), "=r"(r[3]) : "r"(addr));
}
__device__ __forceinline__ void mma16816(float* c, const uint32_t* a, const uint32_t* b) {
    asm volatile("mma.sync.aligned.m16n8k16.row.col.f32.bf16.bf16.f32 "
        "{%0,%1,%2,%3}, {%4,%5,%6,%7}, {%8,%9}, {%0,%1,%2,%3};"
        : "+f"(c[0]), "+f"(c[1]), "+f"(c[2]), "+f"(c[3])
        : "r"(a[0]), "r"(a[1]), "r"(a[2]), "r"(a[3]), "r"(b[0]), "r"(b[1]));
}

// ---------------- small helpers ----------------
__device__ __forceinline__ float block_sum256(float v, float* red, int h, int lane) {
    #pragma unroll
    for (int o = 16; o; o >>= 1) v += __shfl_xor_sync(0xffffffffu, v, o);
    if (lane == 0) red[h] = v;
    __syncthreads();
    float s = red[0] + red[1] + red[2] + red[3] + red[4] + red[5] + red[6] + red[7];
    __syncthreads();
    return s;
}

// ---------------- kernel 0: pack transposed split weights + bias ----------------
__global__ void pack_w_kernel(const float* __restrict__ wq, const float* __restrict__ wk,
                              const float* __restrict__ wv, const float* __restrict__ wo,
                              const float* __restrict__ bq, const float* __restrict__ bk,
                              const float* __restrict__ bv) {
    int idx = blockIdx.x * 256 + threadIdx.x;   // 0 .. 196607
    int n = idx / 256, k = idx % 256;
    float w = (n < 256) ? wq[k * 256 + n]
            : (n < 512) ? wk[k * 256 + (n - 256)]
                        : wv[k * 256 + (n - 512)];
    __nv_bfloat16 h = __float2bfloat16(w);
    g_wqkvTh[idx] = h;
    g_wqkvTl[idx] = __float2bfloat16(w - __bfloat162float(h));
    if (idx < 65536) {
        float w2 = wo[k * 256 + n];
        __nv_bfloat16 h2 = __float2bfloat16(w2);
        g_woTh[idx] = h2;
        g_woTl[idx] = __float2bfloat16(w2 - __bfloat162float(h2));
    }
    if (idx < 768) {
        g_bias[idx] = (idx < 256) ? bq[idx] : (idx < 512) ? bk[idx - 256] : bv[idx - 512];
    }
}

// ---------------- kernel 1: LayerNorm1 -> split bf16 ----------------
__global__ void ln1_kernel(const float* __restrict__ x, const float* __restrict__ g,
                           const float* __restrict__ bt) {
    __shared__ float red[8];
    int row = blockIdx.x, tid = threadIdx.x;
    size_t off = (size_t)row * DD + tid;
    float v = x[off];
    float mu = block_sum256(v, red, tid >> 5, tid & 31) * (1.f / 256.f);
    float d = v - mu;
    float var = block_sum256(d * d, red, tid >> 5, tid & 31) * (1.f / 256.f);
    float y = d * rsqrtf(var + LN_EPS) * g[tid] + bt[tid];
    __nv_bfloat16 h = __float2bfloat16(y);
    g_xnh[off] = h;
    g_xnl[off] = __float2bfloat16(y - __bfloat162float(h));
}

// ---------------- HMMA GEMM ----------------
// C[M x Ncols] = (Ah+Al)[M x 256] @ (Bh+Bl)^T + bias, bf16 3-term split, fp32 accum.
// B (N-major BT[n][k]) persistent in SMEM for full K=256 (hi+lo).
// A chunks (BK=32) cp.async double-buffered. 256 threads, warp grid 2(M)x4(N),
// warp tile 64x32, mma.sync m16n8k16 fragments via ldmatrix.x4.
#define BPITCH 528            // 512B data + 16B pad: rows advance 4 banks -> conflict-free
#define APITCH 80             // 64B data + 16B pad: rows advance 20 banks -> conflict-free
#define B_TERM (128 * BPITCH)             // 67584
#define OFF_A  (2 * B_TERM)               // 135168
#define A_TERM (128 * APITCH)             // 10240
#define A_BUF  (2 * A_TERM)               // 20480
#define SMEM_TOTAL_GEMM (OFF_A + 2 * A_BUF)   // 176128

__device__ __forceinline__ void issue_A_chunk(uint32_t sb, int buf,
        const __nv_bfloat16* __restrict__ Ah, const __nv_bfloat16* __restrict__ Al,
        int row0, int kc, int tid) {
    #pragma unroll
    for (int t = 0; t < 2; t++) {
        const __nv_bfloat16* src = t ? Al : Ah;
        #pragma unroll
        for (int rep = 0; rep < 2; rep++) {
            int idx = rep * 256 + tid;          // 0..511
            int row = idx >> 2, cc = idx & 3;
            uint32_t dst = sb + OFF_A + buf * A_BUF + t * A_TERM + row * APITCH + cc * 16;
            cp_async16(dst, src + (size_t)(row0 + row) * 256 + kc * 32 + cc * 8);
        }
    }
}

template<bool FUSE_OUT>
__global__ void __launch_bounds__(256, 1)
hmma_gemm_kernel(const __nv_bfloat16* __restrict__ Ah, const __nv_bfloat16* __restrict__ Al,
                 const __nv_bfloat16* __restrict__ BTh, const __nv_bfloat16* __restrict__ BTl,
                 const float* __restrict__ bias, const float* __restrict__ add,
                 float* __restrict__ C, int M, int Ncols) {
    extern __shared__ __align__(1024) char smem[];
    const uint32_t sb = smem_to_u32(smem);
    const int tid = threadIdx.x;
    const int lane = tid & 31;
    const int wid = tid >> 5;
    const int wm = wid & 1;       // 0..1  (M dir, 64 rows each)
    const int wn = wid >> 1;      // 0..3  (N dir, 32 cols each)
    const int n0 = blockIdx.x * 128;

    // ---- load persistent B (hi+lo, full K) ----
    #pragma unroll
    for (int t = 0; t < 2; t++) {
        const __nv_bfloat16* src = t ? BTl : BTh;
        #pragma unroll
        for (int j = 0; j < 16; j++) {
            int idx = j * 256 + tid;            // 0..4095
            int row = idx >> 5, cc = idx & 31;
            uint32_t dst = sb + t * B_TERM + row * BPITCH + cc * 16;
            cp_async16(dst, src + (size_t)(n0 + row) * 256 + cc * 8);
        }
    }

    // per-thread fragment address components
    const uint32_t a_lane_off = (uint32_t)((lane & 15) * APITCH + (lane >> 4) * 16);
    const int b_row = wn * 32 + ((lane >> 4) << 3) + (lane & 7);
    const uint32_t b_lane_off = (uint32_t)(b_row * BPITCH + ((lane >> 3) & 1) * 16);

    const int ntiles = (M + 127) >> 7;

    for (int mt = blockIdx.y; mt < ntiles; mt += gridDim.y) {
        const int row0 = mt << 7;

        float acc[4][4][4];
        #pragma unroll
        for (int i = 0; i < 4; i++)
            #pragma unroll
            for (int j = 0; j < 4; j++)
                #pragma unroll
                for (int r = 0; r < 4; r++) acc[i][j][r] = 0.f;

        issue_A_chunk(sb, 0, Ah, Al, row0, 0, tid);
        CP_COMMIT();

        #pragma unroll 1
        for (int c = 0; c < 8; c++) {
            if (c < 7) {
                issue_A_chunk(sb, (c + 1) & 1, Ah, Al, row0, c + 1, tid);
                CP_COMMIT();
                CP_WAIT(1);
            } else {
                CP_WAIT(0);
            }
            __syncthreads();

            const uint32_t abase = sb + OFF_A + (c & 1) * A_BUF + (wm * 64) * APITCH + a_lane_off;
            #pragma unroll
            for (int q = 0; q < 2; q++) {
                uint32_t ah[4][4], al[4][4], bh[2][4], bl[2][4];
                #pragma unroll
                for (int mf = 0; mf < 4; mf++) {
                    ldsm4(ah[mf], abase + mf * 16 * APITCH + q * 32);
                    ldsm4(al[mf], abase + A_TERM + mf * 16 * APITCH + q * 32);
                }
                const int kk = c * 2 + q;
                const uint32_t bbase = sb + b_lane_off + kk * 32;
                #pragma unroll
                for (int p = 0; p < 2; p++) {
                    ldsm4(bh[p], bbase + p * 16 * BPITCH);
                    ldsm4(bl[p], bbase + B_TERM + p * 16 * BPITCH);
                }
                #pragma unroll
                for (int mf = 0; mf < 4; mf++) {
                    #pragma unroll
                    for (int nf = 0; nf < 4; nf++) {
                        const uint32_t* bph = &bh[nf >> 1][(nf & 1) * 2];
                        const uint32_t* bpl = &bl[nf >> 1][(nf & 1) * 2];
                        mma16816(acc[mf][nf], ah[mf], bph);
                        mma16816(acc[mf][nf], ah[mf], bpl);
                        mma16816(acc[mf][nf], al[mf], bph);
                    }
                }
            }
            __syncthreads();
        }

        // ---- epilogue: direct fused stores ----
        const int colb = n0 + wn * 32 + (lane & 3) * 2;
        #pragma unroll
        for (int mf = 0; mf < 4; mf++) {
            const int r1 = row0 + wm * 64 + mf * 16 + (lane >> 2);
            const int r2 = r1 + 8;
            #pragma unroll
            for (int nf = 0; nf < 4; nf++) {
                const int gc = colb + nf * 8;
                float2 b2 = *(const float2*)(bias + gc);
                float2 v1 = make_float2(acc[mf][nf][0] + b2.x, acc[mf][nf][1] + b2.y);
                float2 v2 = make_float2(acc[mf][nf][2] + b2.x, acc[mf][nf][3] + b2.y);
                if (r1 < M) {
                    if (FUSE_OUT) {
                        float2 a1 = *(const float2*)(add + (size_t)r1 * Ncols + gc);
                        v1.x = fmaxf(v1.x, 0.f) + a1.x;
                        v1.y = fmaxf(v1.y, 0.f) + a1.y;
                    }
                    *(float2*)(C + (size_t)r1 * Ncols + gc) = v1;
                }
                if (r2 < M) {
                    if (FUSE_OUT) {
                        float2 a2 = *(const float2*)(add + (size_t)r2 * Ncols + gc);
                        v2.x = fmaxf(v2.x, 0.f) + a2.x;
                        v2.y = fmaxf(v2.y, 0.f) + a2.y;
                    }
                    *(float2*)(C + (size_t)r2 * Ncols + gc) = v2;
                }
            }
        }
        __syncthreads();
    }
}

// ---------------- kernel 3: attention + residual + LayerNorm2 ----------------
// 4 nodes per block; 64 threads per node; each thread handles 4 channels (float4).
// K rows batched up-front for MLP; then independent v-pass.
__global__ void __launch_bounds__(256)
attn_ln2_kernel(const int* __restrict__ e32,
                const float* __restrict__ gamma2, const float* __restrict__ beta2) {
    __shared__ int sdst[4][8];
    __shared__ int ssrc[4];
    __shared__ float red[4][2];
    __shared__ float red2[4][2];
    const int tid = threadIdx.x;
    const int sub = tid >> 6;          // node within block
    const int t = tid & 63;            // thread within node
    const int gnode = blockIdx.x * 4 + sub;   // 0 .. 39999
    const int b = (gnode >= NN) ? 1 : 0;
    const int i = gnode - b * NN;

    if (t < 8) {
        bool is64 = ((e32[1] | e32[3] | e32[5] | e32[7] |
                      e32[9] | e32[11] | e32[13] | e32[15]) == 0);
        int e = i * DEG + t;
        sdst[sub][t] = is64 ? e32[4 * e + 2] : e32[2 * e + 1];
        if (t == 0) ssrc[sub] = is64 ? e32[4 * e] : e32[2 * e];
    }
    __syncthreads();

    const int s = ssrc[sub];
    const int ch = (t >> 3) * 32 + (t & 7) * 4;   // channel group base
    const size_t rowq = (size_t)(b * NN + s) * 768;
    const float4 qv = *(const float4*)(g_qkv + rowq + ch);

    size_t rk[DEG];
    #pragma unroll
    for (int j = 0; j < DEG; j++)
        rk[j] = (size_t)(b * NN + sdst[sub][j]) * 768 + 256 + ch;

    // phase 1: batch all 8 k loads (8 LDG.128 in flight), partial dots
    float p[DEG];
    #pragma unroll
    for (int j = 0; j < DEG; j++) {
        float4 kv = *(const float4*)(g_qkv + rk[j]);
        p[j] = qv.x * kv.x + qv.y * kv.y + qv.z * kv.z + qv.w * kv.w;
    }
    // phase 2: reduce within 8-lane head groups, exp
    float w[DEG], den = 0.f;
    #pragma unroll
    for (int j = 0; j < DEG; j++) {
        float pj = p[j];
        pj += __shfl_xor_sync(0xffffffffu, pj, 1);
        pj += __shfl_xor_sync(0xffffffffu, pj, 2);
        pj += __shfl_xor_sync(0xffffffffu, pj, 4);
        w[j] = __expf(pj * INV_SQRT_DH);
        den += w[j];
    }
    // phase 3: v pass (8 independent loads + FMA)
    float4 num = make_float4(0.f, 0.f, 0.f, 0.f);
    #pragma unroll
    for (int j = 0; j < DEG; j++) {
        float4 vv = *(const float4*)(g_qkv + rk[j] + 256);
        num.x += w[j] * vv.x; num.y += w[j] * vv.y;
        num.z += w[j] * vv.z; num.w += w[j] * vv.w;
    }
    const float inv = 1.f / den;

    const size_t off = (size_t)(b * NN + s) * DD + ch;
    union { uint2 u; __nv_bfloat162 b2[2]; } uh, ul;
    uh.u = *(const uint2*)(g_xnh + off);
    ul.u = *(const uint2*)(g_xnl + off);
    float2 h01 = __bfloat1622float2(uh.b2[0]);
    float2 h23 = __bfloat1622float2(uh.b2[1]);
    float2 l01 = __bfloat1622float2(ul.b2[0]);
    float2 l23 = __bfloat1622float2(ul.b2[1]);

    float c0 = h01.x + l01.x + num.x * inv;
    float c1 = h01.y + l01.y + num.y * inv;
    float c2 = h23.x + l23.x + num.z * inv;
    float c3 = h23.y + l23.y + num.w * inv;

    // LN over 256 channels spread across 64 threads (2 warps)
    float ls = c0 + c1 + c2 + c3;
    #pragma unroll
    for (int o = 16; o; o >>= 1) ls += __shfl_xor_sync(0xffffffffu, ls, o);
    if ((t & 31) == 0) red[sub][t >> 5] = ls;
    __syncthreads();
    float mu = (red[sub][0] + red[sub][1]) * (1.f / 256.f);

    float d0 = c0 - mu, d1 = c1 - mu, d2 = c2 - mu, d3 = c3 - mu;
    float lv = d0 * d0 + d1 * d1 + d2 * d2 + d3 * d3;
    #pragma unroll
    for (int o = 16; o; o >>= 1) lv += __shfl_xor_sync(0xffffffffu, lv, o);
    if ((t & 31) == 0) red2[sub][t >> 5] = lv;
    __syncthreads();
    float var = (red2[sub][0] + red2[sub][1]) * (1.f / 256.f);
    float rs = rsqrtf(var + LN_EPS);

    float4 gm = *(const float4*)(gamma2 + ch);
    float4 bt = *(const float4*)(beta2 + ch);
    float t0 = d0 * rs * gm.x + bt.x;
    float t1 = d1 * rs * gm.y + bt.y;
    float t2 = d2 * rs * gm.z + bt.z;
    float t3 = d3 * rs * gm.w + bt.w;

    *(float4*)(g_concat + off) = make_float4(c0, c1, c2, c3);

    __nv_bfloat16 th0 = __float2bfloat16(t0), th1 = __float2bfloat16(t1);
    __nv_bfloat16 th2 = __float2bfloat16(t2), th3 = __float2bfloat16(t3);
    union { uint2 u; __nv_bfloat16 h[4]; } oh, ol;
    oh.h[0] = th0; oh.h[1] = th1; oh.h[2] = th2; oh.h[3] = th3;
    ol.h[0] = __float2bfloat16(t0 - __bfloat162float(th0));
    ol.h[1] = __float2bfloat16(t1 - __bfloat162float(th1));
    ol.h[2] = __float2bfloat16(t2 - __bfloat162float(th2));
    ol.h[3] = __float2bfloat16(t3 - __bfloat162float(th3));
    *(uint2*)(g_th + off) = oh.u;
    *(uint2*)(g_tl + off) = ol.u;
}

// ---------------- launch ----------------
extern "C" void kernel_launch(void* const* d_in, const int* in_sizes, int n_in,
                              void* d_out, int out_size) {
    const float* x      = (const float*)d_in[0];
    const int*   edges  = (const int*)d_in[1];
    const float* wq     = (const float*)d_in[2];
    const float* bq     = (const float*)d_in[3];
    const float* wk     = (const float*)d_in[4];
    const float* bk     = (const float*)d_in[5];
    const float* wv     = (const float*)d_in[6];
    const float* bv     = (const float*)d_in[7];
    const float* wo     = (const float*)d_in[8];
    const float* bo     = (const float*)d_in[9];
    const float* gamma1 = (const float*)d_in[10];
    const float* beta1  = (const float*)d_in[11];
    const float* gamma2 = (const float*)d_in[12];
    const float* beta2  = (const float*)d_in[13];
    float* out = (float*)d_out;

    __nv_bfloat16 *xnh, *xnl, *th, *tl, *wTh, *wTl, *woTh, *woTl;
    float *qkv_p, *bias_p, *concat_p;
    cudaGetSymbolAddress((void**)&xnh,  g_xnh);
    cudaGetSymbolAddress((void**)&xnl,  g_xnl);
    cudaGetSymbolAddress((void**)&th,   g_th);
    cudaGetSymbolAddress((void**)&tl,   g_tl);
    cudaGetSymbolAddress((void**)&wTh,  g_wqkvTh);
    cudaGetSymbolAddress((void**)&wTl,  g_wqkvTl);
    cudaGetSymbolAddress((void**)&woTh, g_woTh);
    cudaGetSymbolAddress((void**)&woTl, g_woTl);
    cudaGetSymbolAddress((void**)&qkv_p,    g_qkv);
    cudaGetSymbolAddress((void**)&bias_p,   g_bias);
    cudaGetSymbolAddress((void**)&concat_p, g_concat);

    cudaFuncSetAttribute(hmma_gemm_kernel<false>,
        cudaFuncAttributeMaxDynamicSharedMemorySize, SMEM_TOTAL_GEMM);
    cudaFuncSetAttribute(hmma_gemm_kernel<true>,
        cudaFuncAttributeMaxDynamicSharedMemorySize, SMEM_TOTAL_GEMM);

    // 0) pack transposed split weights
    pack_w_kernel<<<768, 256>>>(wq, wk, wv, wo, bq, bk, bv);
    // 1) LayerNorm1 -> bf16 hi/lo
    ln1_kernel<<<ROWS, 256>>>(x, gamma1, beta1);
    // 2) QKV projection (HMMA): [40000 x 256] @ [256 x 768]
    //    144 CTAs = one full wave at 1 CTA/SM (148 SMs); 150 caused a 2-CTA tail wave.
    {
        dim3 grid(6, 24);
        hmma_gemm_kernel<false><<<grid, 256, SMEM_TOTAL_GEMM>>>(
            xnh, xnl, wTh, wTl, bias_p, nullptr, qkv_p, ROWS, 768);
    }
    // 3) attention + residual + LayerNorm2 (4 nodes / block)
    attn_ln2_kernel<<<ROWS / 4, 256>>>(edges, gamma2, beta2);
    // 4) output projection (HMMA) + ReLU + residual
    {
        dim3 grid(2, 74);
        hmma_gemm_kernel<true><<<grid, 256, SMEM_TOTAL_GEMM>>>(
            th, tl, woTh, woTl, bo, concat_p, out, ROWS, 256);
    }
}

// round 5
// speedup vs baseline: 1.4177x; 1.4177x over previous
#include <cuda_runtime.h>
#include <cuda_fp16.h>
#include <cstdint>
#include <math.h>

// Problem constants (fixed by reference setup_inputs)
#define BB 2
#define NN 20000
#define DD 256
#define HH 8
#define DH 32
#define DEG 8
#define ROWS (BB*NN)          // 40000
#define PADROWS 40064         // padded to multiple of 128 for unguarded tile loads
#define LN_EPS 1e-3f
#define INV_SQRT_DH 0.17677669529663687f  // 1/sqrt(32)

// ---------------- scratch (device globals; no allocations allowed) ----------------
__device__ __half g_xnh[(size_t)PADROWS * DD];   // LN1 out hi (fp16)
__device__ __half g_xnl[(size_t)PADROWS * DD];   // LN1 out lo (fp16)
__device__ __half g_th [(size_t)PADROWS * DD];   // LN2 out hi
__device__ __half g_tl [(size_t)PADROWS * DD];   // LN2 out lo
__device__ __half g_qkv[(size_t)ROWS * 3 * DD];  // q|k|v per row (fp16, 61MB, L2-resident)
__device__ float g_concat[(size_t)ROWS * DD];    // xn + attn (fp32)
__device__ float g_bias[768];                    // packed [bq|bk|bv]
__device__ __half g_wqkvT[768 * 256];            // W^T fp16 [n][k]
__device__ __half g_woT[256 * 256];              // wo^T fp16

// ---------------- PTX helpers (sm_80-era: valid on base sm_103 target) ----------------
__device__ __forceinline__ void cp_async16(uint32_t dst, const void* src) {
    asm volatile("cp.async.cg.shared.global [%0], [%1], 16;" :: "r"(dst), "l"(src));
}
#define CP_COMMIT() asm volatile("cp.async.commit_group;" ::: "memory")
#define CP_WAIT(n)  asm volatile("cp.async.wait_group %0;" :: "n"(n) : "memory")

__device__ __forceinline__ uint32_t smem_to_u32(const void* p) {
    uint32_t a;
    asm("{ .reg .u64 t; cvta.to.shared.u64 t, %1; cvt.u32.u64 %0, t; }" : "=r"(a) : "l"(p));
    return a;
}
__device__ __forceinline__ void ldsm4(uint32_t* r, uint32_t addr) {
    asm volatile("ldmatrix.sync.aligned.m8n8.x4.shared.b16 {%0,%1,%2,%3}, [%4];"
        : "=r"(r[0]), "=r"(r[1]), "=r"(r[2]), "=r"(r[3]) : "r"(addr));
}
__device__ __forceinline__ void mma16816(float* c, const uint32_t* a, const uint32_t* b) {
    asm volatile("mma.sync.aligned.m16n8k16.row.col.f32.f16.f16.f32 "
        "{%0,%1,%2,%3}, {%4,%5,%6,%7}, {%8,%9}, {%0,%1,%2,%3};"
        : "+f"(c[0]), "+f"(c[1]), "+f"(c[2]), "+f"(c[3])
        : "r"(a[0]), "r"(a[1]), "r"(a[2]), "r"(a[3]), "r"(b[0]), "r"(b[1]));
}

// ---------------- small helpers ----------------
__device__ __forceinline__ float block_sum256(float v, float* red, int h, int lane) {
    #pragma unroll
    for (int o = 16; o; o >>= 1) v += __shfl_xor_sync(0xffffffffu, v, o);
    if (lane == 0) red[h] = v;
    __syncthreads();
    float s = red[0] + red[1] + red[2] + red[3] + red[4] + red[5] + red[6] + red[7];
    __syncthreads();
    return s;
}

// ---------------- kernel 0: pack transposed fp16 weights + bias ----------------
__global__ void pack_w_kernel(const float* __restrict__ wq, const float* __restrict__ wk,
                              const float* __restrict__ wv, const float* __restrict__ wo,
                              const float* __restrict__ bq, const float* __restrict__ bk,
                              const float* __restrict__ bv) {
    int idx = blockIdx.x * 256 + threadIdx.x;   // 0 .. 196607
    int n = idx / 256, k = idx % 256;
    float w = (n < 256) ? wq[k * 256 + n]
            : (n < 512) ? wk[k * 256 + (n - 256)]
                        : wv[k * 256 + (n - 512)];
    g_wqkvT[idx] = __float2half(w);
    if (idx < 65536) g_woT[idx] = __float2half(wo[k * 256 + n]);
    if (idx < 768) {
        g_bias[idx] = (idx < 256) ? bq[idx] : (idx < 512) ? bk[idx - 256] : bv[idx - 512];
    }
}

// ---------------- kernel 1: LayerNorm1 -> split fp16 ----------------
__global__ void ln1_kernel(const float* __restrict__ x, const float* __restrict__ g,
                           const float* __restrict__ bt) {
    __shared__ float red[8];
    int row = blockIdx.x, tid = threadIdx.x;
    size_t off = (size_t)row * DD + tid;
    float v = x[off];
    float mu = block_sum256(v, red, tid >> 5, tid & 31) * (1.f / 256.f);
    float d = v - mu;
    float var = block_sum256(d * d, red, tid >> 5, tid & 31) * (1.f / 256.f);
    float y = d * rsqrtf(var + LN_EPS) * g[tid] + bt[tid];
    __half h = __float2half(y);
    g_xnh[off] = h;
    g_xnl[off] = __float2half(y - __half2float(h));
}

// ---------------- HMMA GEMM (2-term asymmetric fp16 split) ----------------
// C[M x Ncols] = (Ah+Al)[M x 256] @ B^T + bias; A split fp16 hi/lo, B single fp16.
// Error = B's fp16 rounding only (~2^-12 per product, ~5e-5 aggregated).
// B (N-major BT[n][k]) persistent in SMEM for full K=256 (single term, 66KB).
// A chunks (BK=32, hi+lo) cp.async double-buffered. 256 threads, warps 2(M)x4(N),
// warp tile 64x32. SMEM ~106KB -> 2 CTAs/SM.
#define BPITCH 528            // 512B data + 16B pad
#define APITCH 80             // 64B data + 16B pad
#define OFF_A  (128 * BPITCH)             // 67584
#define A_TERM (128 * APITCH)             // 10240
#define A_BUF  (2 * A_TERM)               // hi+lo per chunk: 20480
#define SMEM_TOTAL_GEMM (OFF_A + 2 * A_BUF)   // 108544

__device__ __forceinline__ void issue_A_chunk(uint32_t sb, int buf,
        const __half* __restrict__ Ah, const __half* __restrict__ Al,
        int row0, int kc, int tid) {
    #pragma unroll
    for (int t = 0; t < 2; t++) {
        const __half* src = t ? Al : Ah;
        #pragma unroll
        for (int rep = 0; rep < 2; rep++) {
            int idx = rep * 256 + tid;          // 0..511
            int row = idx >> 2, cc = idx & 3;
            uint32_t dst = sb + OFF_A + buf * A_BUF + t * A_TERM + row * APITCH + cc * 16;
            cp_async16(dst, src + (size_t)(row0 + row) * 256 + kc * 32 + cc * 8);
        }
    }
}

template<bool FUSE_OUT>
__global__ void __launch_bounds__(256, 2)
hmma_gemm_kernel(const __half* __restrict__ Ah, const __half* __restrict__ Al,
                 const __half* __restrict__ BT,
                 const float* __restrict__ bias, const float* __restrict__ add,
                 void* __restrict__ Cout, int M, int Ncols) {
    extern __shared__ __align__(1024) char smem[];
    const uint32_t sb = smem_to_u32(smem);
    const int tid = threadIdx.x;
    const int lane = tid & 31;
    const int wid = tid >> 5;
    const int wm = wid & 1;       // M dir, 64 rows each
    const int wn = wid >> 1;      // N dir, 32 cols each
    const int n0 = blockIdx.x * 128;

    // ---- load persistent B (single fp16 term, full K) ----
    #pragma unroll
    for (int j = 0; j < 16; j++) {
        int idx = j * 256 + tid;            // 0..4095
        int row = idx >> 5, cc = idx & 31;
        uint32_t dst = sb + row * BPITCH + cc * 16;
        cp_async16(dst, BT + (size_t)(n0 + row) * 256 + cc * 8);
    }

    const uint32_t a_lane_off = (uint32_t)((lane & 15) * APITCH + (lane >> 4) * 16);
    const int b_row = wn * 32 + ((lane >> 4) << 3) + (lane & 7);
    const uint32_t b_lane_off = (uint32_t)(b_row * BPITCH + ((lane >> 3) & 1) * 16);

    const int ntiles = (M + 127) >> 7;

    for (int mt = blockIdx.y; mt < ntiles; mt += gridDim.y) {
        const int row0 = mt << 7;

        float acc[4][4][4];
        #pragma unroll
        for (int i = 0; i < 4; i++)
            #pragma unroll
            for (int j = 0; j < 4; j++)
                #pragma unroll
                for (int r = 0; r < 4; r++) acc[i][j][r] = 0.f;

        issue_A_chunk(sb, 0, Ah, Al, row0, 0, tid);
        CP_COMMIT();

        #pragma unroll 1
        for (int c = 0; c < 8; c++) {
            if (c < 7) {
                issue_A_chunk(sb, (c + 1) & 1, Ah, Al, row0, c + 1, tid);
                CP_COMMIT();
                CP_WAIT(1);
            } else {
                CP_WAIT(0);
            }
            __syncthreads();

            const uint32_t abase = sb + OFF_A + (c & 1) * A_BUF + (wm * 64) * APITCH + a_lane_off;
            #pragma unroll
            for (int q = 0; q < 2; q++) {
                uint32_t ah[4][4], al[4][4], bh[2][4];
                #pragma unroll
                for (int mf = 0; mf < 4; mf++) {
                    ldsm4(ah[mf], abase + mf * 16 * APITCH + q * 32);
                    ldsm4(al[mf], abase + A_TERM + mf * 16 * APITCH + q * 32);
                }
                const int kk = c * 2 + q;
                const uint32_t bbase = sb + b_lane_off + kk * 32;
                #pragma unroll
                for (int p = 0; p < 2; p++) ldsm4(bh[p], bbase + p * 16 * BPITCH);
                #pragma unroll
                for (int mf = 0; mf < 4; mf++) {
                    #pragma unroll
                    for (int nf = 0; nf < 4; nf++) {
                        const uint32_t* bp = &bh[nf >> 1][(nf & 1) * 2];
                        mma16816(acc[mf][nf], ah[mf], bp);
                        mma16816(acc[mf][nf], al[mf], bp);
                    }
                }
            }
            __syncthreads();
        }

        // ---- epilogue ----
        const int colb = n0 + wn * 32 + (lane & 3) * 2;
        #pragma unroll
        for (int mf = 0; mf < 4; mf++) {
            const int r1 = row0 + wm * 64 + mf * 16 + (lane >> 2);
            const int r2 = r1 + 8;
            #pragma unroll
            for (int nf = 0; nf < 4; nf++) {
                const int gc = colb + nf * 8;
                float2 b2 = *(const float2*)(bias + gc);
                float2 v1 = make_float2(acc[mf][nf][0] + b2.x, acc[mf][nf][1] + b2.y);
                float2 v2 = make_float2(acc[mf][nf][2] + b2.x, acc[mf][nf][3] + b2.y);
                if (FUSE_OUT) {
                    float* C = (float*)Cout;
                    if (r1 < M) {
                        float2 a1 = *(const float2*)(add + (size_t)r1 * Ncols + gc);
                        v1.x = fmaxf(v1.x, 0.f) + a1.x;
                        v1.y = fmaxf(v1.y, 0.f) + a1.y;
                        *(float2*)(C + (size_t)r1 * Ncols + gc) = v1;
                    }
                    if (r2 < M) {
                        float2 a2 = *(const float2*)(add + (size_t)r2 * Ncols + gc);
                        v2.x = fmaxf(v2.x, 0.f) + a2.x;
                        v2.y = fmaxf(v2.y, 0.f) + a2.y;
                        *(float2*)(C + (size_t)r2 * Ncols + gc) = v2;
                    }
                } else {
                    __half* C = (__half*)Cout;
                    if (r1 < M)
                        *(__half2*)(C + (size_t)r1 * Ncols + gc) = __floats2half2_rn(v1.x, v1.y);
                    if (r2 < M)
                        *(__half2*)(C + (size_t)r2 * Ncols + gc) = __floats2half2_rn(v2.x, v2.y);
                }
            }
        }
        __syncthreads();
    }
}

// ---------------- kernel 3: attention + residual + LayerNorm2 ----------------
// One WARP per node (8 nodes/block). Each lane owns 8 channels (16B fp16 loads).
// qkv in fp16 (61MB, L2-resident). No __syncthreads — all warp-shfl.
__global__ void __launch_bounds__(256)
attn_ln2_kernel(const int* __restrict__ e32,
                const float* __restrict__ gamma2, const float* __restrict__ beta2) {
    const int tid = threadIdx.x;
    const int w = tid >> 5, lane = tid & 31;
    const int gnode = blockIdx.x * 8 + w;     // 0 .. 39999
    const int b = (gnode >= NN) ? 1 : 0;
    const int i = gnode - b * NN;

    // edge layout detection (int64 high words are all zero)
    const bool is64 = ((e32[1] | e32[3] | e32[5] | e32[7] |
                        e32[9] | e32[11] | e32[13] | e32[15]) == 0);
    int myd = 0;
    if (lane < 8) {
        int e = i * DEG + lane;
        myd = is64 ? e32[4 * e + 2] : e32[2 * e + 1];
    }
    const int s = is64 ? e32[4 * (i * DEG)] : e32[2 * (i * DEG)];  // same addr -> broadcast

    const int ch = lane * 8;                 // 8 channels per lane
    const size_t rowq = (size_t)(b * NN + s) * 768 + ch;

    // q (8 halves -> 4 half2 -> float2[4])
    union U4 { uint4 u; __half2 h2[4]; };
    U4 qu; qu.u = *(const uint4*)(g_qkv + rowq);
    float2 qf[4];
    #pragma unroll
    for (int p = 0; p < 4; p++) qf[p] = __half22float2(qu.h2[p]);

    size_t rk[DEG];
    #pragma unroll
    for (int j = 0; j < DEG; j++) {
        int dj = __shfl_sync(0xffffffffu, myd, j);
        rk[j] = (size_t)(b * NN + dj) * 768 + 256 + ch;
    }

    // phase 1: all 8 k loads in flight, partial dots
    float pd[DEG];
    #pragma unroll
    for (int j = 0; j < DEG; j++) {
        U4 ku; ku.u = *(const uint4*)(g_qkv + rk[j]);
        float d = 0.f;
        #pragma unroll
        for (int p = 0; p < 4; p++) {
            float2 kf = __half22float2(ku.h2[p]);
            d += qf[p].x * kf.x + qf[p].y * kf.y;
        }
        pd[j] = d;
    }
    // phase 2: reduce within 4-lane head groups (head = 32ch = 4 lanes), exp
    float wj[DEG], den = 0.f;
    #pragma unroll
    for (int j = 0; j < DEG; j++) {
        float p = pd[j];
        p += __shfl_xor_sync(0xffffffffu, p, 1);
        p += __shfl_xor_sync(0xffffffffu, p, 2);
        wj[j] = __expf(p * INV_SQRT_DH);
        den += wj[j];
    }
    // phase 3: v pass
    float num[8];
    #pragma unroll
    for (int q = 0; q < 8; q++) num[q] = 0.f;
    #pragma unroll
    for (int j = 0; j < DEG; j++) {
        U4 vu; vu.u = *(const uint4*)(g_qkv + rk[j] + 256);
        #pragma unroll
        for (int p = 0; p < 4; p++) {
            float2 vf = __half22float2(vu.h2[p]);
            num[2*p]   += wj[j] * vf.x;
            num[2*p+1] += wj[j] * vf.y;
        }
    }
    const float inv = 1.f / den;

    // residual: xn = hi + lo
    const size_t off = (size_t)(b * NN + s) * DD + ch;
    U4 xh, xl;
    xh.u = *(const uint4*)(g_xnh + off);
    xl.u = *(const uint4*)(g_xnl + off);
    float c[8];
    #pragma unroll
    for (int p = 0; p < 4; p++) {
        float2 h2 = __half22float2(xh.h2[p]);
        float2 l2 = __half22float2(xl.h2[p]);
        c[2*p]   = h2.x + l2.x + num[2*p]   * inv;
        c[2*p+1] = h2.y + l2.y + num[2*p+1] * inv;
    }

    // LayerNorm over 256 channels within the warp
    float ls = 0.f;
    #pragma unroll
    for (int q = 0; q < 8; q++) ls += c[q];
    #pragma unroll
    for (int o = 16; o; o >>= 1) ls += __shfl_xor_sync(0xffffffffu, ls, o);
    const float mu = ls * (1.f / 256.f);

    float d[8], lv = 0.f;
    #pragma unroll
    for (int q = 0; q < 8; q++) { d[q] = c[q] - mu; lv += d[q] * d[q]; }
    #pragma unroll
    for (int o = 16; o; o >>= 1) lv += __shfl_xor_sync(0xffffffffu, lv, o);
    const float rs = rsqrtf(lv * (1.f / 256.f) + LN_EPS);

    float4 gm0 = *(const float4*)(gamma2 + ch);
    float4 gm1 = *(const float4*)(gamma2 + ch + 4);
    float4 bt0 = *(const float4*)(beta2 + ch);
    float4 bt1 = *(const float4*)(beta2 + ch + 4);
    float tv[8];
    tv[0] = d[0] * rs * gm0.x + bt0.x;  tv[1] = d[1] * rs * gm0.y + bt0.y;
    tv[2] = d[2] * rs * gm0.z + bt0.z;  tv[3] = d[3] * rs * gm0.w + bt0.w;
    tv[4] = d[4] * rs * gm1.x + bt1.x;  tv[5] = d[5] * rs * gm1.y + bt1.y;
    tv[6] = d[6] * rs * gm1.z + bt1.z;  tv[7] = d[7] * rs * gm1.w + bt1.w;

    *(float4*)(g_concat + off)     = make_float4(c[0], c[1], c[2], c[3]);
    *(float4*)(g_concat + off + 4) = make_float4(c[4], c[5], c[6], c[7]);

    U4 oh, ol;
    #pragma unroll
    for (int p = 0; p < 4; p++) {
        __half h0 = __float2half(tv[2*p]);
        __half h1 = __float2half(tv[2*p+1]);
        oh.h2[p] = __halves2half2(h0, h1);
        ol.h2[p] = __halves2half2(__float2half(tv[2*p]   - __half2float(h0)),
                                  __float2half(tv[2*p+1] - __half2float(h1)));
    }
    *(uint4*)(g_th + off) = oh.u;
    *(uint4*)(g_tl + off) = ol.u;
}

// ---------------- launch ----------------
extern "C" void kernel_launch(void* const* d_in, const int* in_sizes, int n_in,
                              void* d_out, int out_size) {
    const float* x      = (const float*)d_in[0];
    const int*   edges  = (const int*)d_in[1];
    const float* wq     = (const float*)d_in[2];
    const float* bq     = (const float*)d_in[3];
    const float* wk     = (const float*)d_in[4];
    const float* bk     = (const float*)d_in[5];
    const float* wv     = (const float*)d_in[6];
    const float* bv     = (const float*)d_in[7];
    const float* wo     = (const float*)d_in[8];
    const float* bo     = (const float*)d_in[9];
    const float* gamma1 = (const float*)d_in[10];
    const float* beta1  = (const float*)d_in[11];
    const float* gamma2 = (const float*)d_in[12];
    const float* beta2  = (const float*)d_in[13];
    float* out = (float*)d_out;

    __half *xnh, *xnl, *th, *tl, *wT, *woT, *qkv_p;
    float *bias_p, *concat_p;
    cudaGetSymbolAddress((void**)&xnh,  g_xnh);
    cudaGetSymbolAddress((void**)&xnl,  g_xnl);
    cudaGetSymbolAddress((void**)&th,   g_th);
    cudaGetSymbolAddress((void**)&tl,   g_tl);
    cudaGetSymbolAddress((void**)&wT,   g_wqkvT);
    cudaGetSymbolAddress((void**)&woT,  g_woT);
    cudaGetSymbolAddress((void**)&qkv_p,    g_qkv);
    cudaGetSymbolAddress((void**)&bias_p,   g_bias);
    cudaGetSymbolAddress((void**)&concat_p, g_concat);

    cudaFuncSetAttribute(hmma_gemm_kernel<false>,
        cudaFuncAttributeMaxDynamicSharedMemorySize, SMEM_TOTAL_GEMM);
    cudaFuncSetAttribute(hmma_gemm_kernel<true>,
        cudaFuncAttributeMaxDynamicSharedMemorySize, SMEM_TOTAL_GEMM);

    // 0) pack fp16 weights
    pack_w_kernel<<<768, 256>>>(wq, wk, wv, wo, bq, bk, bv);
    // 1) LayerNorm1 -> fp16 hi/lo
    ln1_kernel<<<ROWS, 256>>>(x, gamma1, beta1);
    // 2) QKV projection: [40000 x 256] @ [256 x 768] -> fp16 qkv
    {
        dim3 grid(6, 48);     // 288 CTAs, 2/SM
        hmma_gemm_kernel<false><<<grid, 256, SMEM_TOTAL_GEMM>>>(
            xnh, xnl, wT, bias_p, nullptr, qkv_p, ROWS, 768);
    }
    // 3) attention + residual + LayerNorm2 (warp per node)
    attn_ln2_kernel<<<ROWS / 8, 256>>>(edges, gamma2, beta2);
    // 4) output projection + ReLU + residual -> fp32 out
    {
        dim3 grid(2, 144);    // 288 CTAs, 2/SM
        hmma_gemm_kernel<true><<<grid, 256, SMEM_TOTAL_GEMM>>>(
            th, tl, woT, bo, concat_p, out, ROWS, 256);
    }
}

// round 6
// speedup vs baseline: 1.8190x; 1.2831x over previous
#include <cuda_runtime.h>
#include <cuda_fp16.h>
#include <cstdint>
#include <math.h>

// Problem constants (fixed by reference setup_inputs)
#define BB 2
#define NN 20000
#define DD 256
#define HH 8
#define DH 32
#define DEG 8
#define ROWS (BB*NN)          // 40000
#define PADROWS 40064         // padded to multiple of 128 for unguarded tile loads
#define LN_EPS 1e-3f
#define INV_SQRT_DH 0.17677669529663687f  // 1/sqrt(32)

// ---------------- scratch (device globals; no allocations allowed) ----------------
__device__ __half g_xnh[(size_t)PADROWS * DD];   // LN1 out hi (fp16) — GEMM A input
__device__ __half g_xnl[(size_t)PADROWS * DD];   // LN1 out lo (fp16) — residual accuracy only
__device__ __half g_th [(size_t)PADROWS * DD];   // LN2 out (fp16)
__device__ __half g_qkv[(size_t)ROWS * 3 * DD];  // q|k|v per row (fp16, 61MB, L2-resident)
__device__ float g_concat[(size_t)ROWS * DD];    // xn + attn (fp32)
__device__ float g_bias[768];                    // packed [bq|bk|bv]
__device__ __half g_wqkvT[768 * 256];            // W^T fp16 [n][k]
__device__ __half g_woT[256 * 256];              // wo^T fp16

// ---------------- PTX helpers (sm_80-era: valid on base sm_103 target) ----------------
__device__ __forceinline__ void cp_async16(uint32_t dst, const void* src) {
    asm volatile("cp.async.cg.shared.global [%0], [%1], 16;" :: "r"(dst), "l"(src));
}
#define CP_COMMIT() asm volatile("cp.async.commit_group;" ::: "memory")
#define CP_WAIT(n)  asm volatile("cp.async.wait_group %0;" :: "n"(n) : "memory")

__device__ __forceinline__ uint32_t smem_to_u32(const void* p) {
    uint32_t a;
    asm("{ .reg .u64 t; cvta.to.shared.u64 t, %1; cvt.u32.u64 %0, t; }" : "=r"(a) : "l"(p));
    return a;
}
__device__ __forceinline__ void ldsm4(uint32_t* r, uint32_t addr) {
    asm volatile("ldmatrix.sync.aligned.m8n8.x4.shared.b16 {%0,%1,%2,%3}, [%4];"
        : "=r"(r[0]), "=r"(r[1]), "=r"(r[2]), "=r"(r[3]) : "r"(addr));
}
__device__ __forceinline__ void mma16816(float* c, const uint32_t* a, const uint32_t* b) {
    asm volatile("mma.sync.aligned.m16n8k16.row.col.f32.f16.f16.f32 "
        "{%0,%1,%2,%3}, {%4,%5,%6,%7}, {%8,%9}, {%0,%1,%2,%3};"
        : "+f"(c[0]), "+f"(c[1]), "+f"(c[2]), "+f"(c[3])
        : "r"(a[0]), "r"(a[1]), "r"(a[2]), "r"(a[3]), "r"(b[0]), "r"(b[1]));
}

// ---------------- small helpers ----------------
__device__ __forceinline__ float block_sum256(float v, float* red, int h, int lane) {
    #pragma unroll
    for (int o = 16; o; o >>= 1) v += __shfl_xor_sync(0xffffffffu, v, o);
    if (lane == 0) red[h] = v;
    __syncthreads();
    float s = red[0] + red[1] + red[2] + red[3] + red[4] + red[5] + red[6] + red[7];
    __syncthreads();
    return s;
}

// ---------------- kernel 0: pack transposed fp16 weights + bias ----------------
__global__ void pack_w_kernel(const float* __restrict__ wq, const float* __restrict__ wk,
                              const float* __restrict__ wv, const float* __restrict__ wo,
                              const float* __restrict__ bq, const float* __restrict__ bk,
                              const float* __restrict__ bv) {
    int idx = blockIdx.x * 256 + threadIdx.x;   // 0 .. 196607
    int n = idx / 256, k = idx % 256;
    float w = (n < 256) ? wq[k * 256 + n]
            : (n < 512) ? wk[k * 256 + (n - 256)]
                        : wv[k * 256 + (n - 512)];
    g_wqkvT[idx] = __float2half(w);
    if (idx < 65536) g_woT[idx] = __float2half(wo[k * 256 + n]);
    if (idx < 768) {
        g_bias[idx] = (idx < 256) ? bq[idx] : (idx < 512) ? bk[idx - 256] : bv[idx - 512];
    }
}

// ---------------- kernel 1: LayerNorm1 -> fp16 hi (+ lo for residual path) ----------------
__global__ void ln1_kernel(const float* __restrict__ x, const float* __restrict__ g,
                           const float* __restrict__ bt) {
    __shared__ float red[8];
    int row = blockIdx.x, tid = threadIdx.x;
    size_t off = (size_t)row * DD + tid;
    float v = x[off];
    float mu = block_sum256(v, red, tid >> 5, tid & 31) * (1.f / 256.f);
    float d = v - mu;
    float var = block_sum256(d * d, red, tid >> 5, tid & 31) * (1.f / 256.f);
    float y = d * rsqrtf(var + LN_EPS) * g[tid] + bt[tid];
    __half h = __float2half(y);
    g_xnh[off] = h;
    g_xnl[off] = __float2half(y - __half2float(h));
}

// ---------------- HMMA GEMM (single-term fp16) ----------------
// C[M x Ncols] = A[M x 256] @ B^T + bias; both operands fp16 (rel_err ~2.5e-4 total,
// measured 1.5e-4 with B-only rounding; threshold 1e-3).
// B (N-major BT[n][k]) persistent in SMEM for full K=256 (66KB).
// A chunks (BK=32) cp.async double-buffered. 256 threads, warps 2(M)x4(N),
// warp tile 64x32. SMEM ~86KB -> 2 CTAs/SM.
#define BPITCH 528            // 512B data + 16B pad
#define APITCH 80             // 64B data + 16B pad
#define OFF_A  (128 * BPITCH)             // 67584
#define A_BUF  (128 * APITCH)             // 10240
#define SMEM_TOTAL_GEMM (OFF_A + 2 * A_BUF)   // 88064

__device__ __forceinline__ void issue_A_chunk(uint32_t sb, int buf,
        const __half* __restrict__ A, int row0, int kc, int tid) {
    #pragma unroll
    for (int rep = 0; rep < 2; rep++) {
        int idx = rep * 256 + tid;          // 0..511
        int row = idx >> 2, cc = idx & 3;
        uint32_t dst = sb + OFF_A + buf * A_BUF + row * APITCH + cc * 16;
        cp_async16(dst, A + (size_t)(row0 + row) * 256 + kc * 32 + cc * 8);
    }
}

template<bool FUSE_OUT>
__global__ void __launch_bounds__(256, 2)
hmma_gemm_kernel(const __half* __restrict__ A,
                 const __half* __restrict__ BT,
                 const float* __restrict__ bias, const float* __restrict__ add,
                 void* __restrict__ Cout, int M, int Ncols) {
    extern __shared__ __align__(1024) char smem[];
    const uint32_t sb = smem_to_u32(smem);
    const int tid = threadIdx.x;
    const int lane = tid & 31;
    const int wid = tid >> 5;
    const int wm = wid & 1;       // M dir, 64 rows each
    const int wn = wid >> 1;      // N dir, 32 cols each
    const int n0 = blockIdx.x * 128;

    // ---- load persistent B (fp16, full K) ----
    #pragma unroll
    for (int j = 0; j < 16; j++) {
        int idx = j * 256 + tid;            // 0..4095
        int row = idx >> 5, cc = idx & 31;
        uint32_t dst = sb + row * BPITCH + cc * 16;
        cp_async16(dst, BT + (size_t)(n0 + row) * 256 + cc * 8);
    }

    const uint32_t a_lane_off = (uint32_t)((lane & 15) * APITCH + (lane >> 4) * 16);
    const int b_row = wn * 32 + ((lane >> 4) << 3) + (lane & 7);
    const uint32_t b_lane_off = (uint32_t)(b_row * BPITCH + ((lane >> 3) & 1) * 16);

    const int ntiles = (M + 127) >> 7;

    for (int mt = blockIdx.y; mt < ntiles; mt += gridDim.y) {
        const int row0 = mt << 7;

        float acc[4][4][4];
        #pragma unroll
        for (int i = 0; i < 4; i++)
            #pragma unroll
            for (int j = 0; j < 4; j++)
                #pragma unroll
                for (int r = 0; r < 4; r++) acc[i][j][r] = 0.f;

        issue_A_chunk(sb, 0, A, row0, 0, tid);
        CP_COMMIT();

        #pragma unroll 1
        for (int c = 0; c < 8; c++) {
            if (c < 7) {
                issue_A_chunk(sb, (c + 1) & 1, A, row0, c + 1, tid);
                CP_COMMIT();
                CP_WAIT(1);
            } else {
                CP_WAIT(0);
            }
            __syncthreads();

            const uint32_t abase = sb + OFF_A + (c & 1) * A_BUF + (wm * 64) * APITCH + a_lane_off;
            #pragma unroll
            for (int q = 0; q < 2; q++) {
                uint32_t ah[4][4], bh[2][4];
                #pragma unroll
                for (int mf = 0; mf < 4; mf++)
                    ldsm4(ah[mf], abase + mf * 16 * APITCH + q * 32);
                const int kk = c * 2 + q;
                const uint32_t bbase = sb + b_lane_off + kk * 32;
                #pragma unroll
                for (int p = 0; p < 2; p++) ldsm4(bh[p], bbase + p * 16 * BPITCH);
                #pragma unroll
                for (int mf = 0; mf < 4; mf++) {
                    #pragma unroll
                    for (int nf = 0; nf < 4; nf++) {
                        const uint32_t* bp = &bh[nf >> 1][(nf & 1) * 2];
                        mma16816(acc[mf][nf], ah[mf], bp);
                    }
                }
            }
            __syncthreads();
        }

        // ---- epilogue ----
        const int colb = n0 + wn * 32 + (lane & 3) * 2;
        #pragma unroll
        for (int mf = 0; mf < 4; mf++) {
            const int r1 = row0 + wm * 64 + mf * 16 + (lane >> 2);
            const int r2 = r1 + 8;
            #pragma unroll
            for (int nf = 0; nf < 4; nf++) {
                const int gc = colb + nf * 8;
                float2 b2 = *(const float2*)(bias + gc);
                float2 v1 = make_float2(acc[mf][nf][0] + b2.x, acc[mf][nf][1] + b2.y);
                float2 v2 = make_float2(acc[mf][nf][2] + b2.x, acc[mf][nf][3] + b2.y);
                if (FUSE_OUT) {
                    float* C = (float*)Cout;
                    if (r1 < M) {
                        float2 a1 = *(const float2*)(add + (size_t)r1 * Ncols + gc);
                        v1.x = fmaxf(v1.x, 0.f) + a1.x;
                        v1.y = fmaxf(v1.y, 0.f) + a1.y;
                        *(float2*)(C + (size_t)r1 * Ncols + gc) = v1;
                    }
                    if (r2 < M) {
                        float2 a2 = *(const float2*)(add + (size_t)r2 * Ncols + gc);
                        v2.x = fmaxf(v2.x, 0.f) + a2.x;
                        v2.y = fmaxf(v2.y, 0.f) + a2.y;
                        *(float2*)(C + (size_t)r2 * Ncols + gc) = v2;
                    }
                } else {
                    __half* C = (__half*)Cout;
                    if (r1 < M)
                        *(__half2*)(C + (size_t)r1 * Ncols + gc) = __floats2half2_rn(v1.x, v1.y);
                    if (r2 < M)
                        *(__half2*)(C + (size_t)r2 * Ncols + gc) = __floats2half2_rn(v2.x, v2.y);
                }
            }
        }
        __syncthreads();
    }
}

// ---------------- kernel 3: attention + residual + LayerNorm2 ----------------
// One WARP per node (8 nodes/block). Each lane owns 8 channels (16B fp16 loads).
// qkv in fp16 (61MB, L2-resident). No __syncthreads — all warp-shfl.
__global__ void __launch_bounds__(256)
attn_ln2_kernel(const int* __restrict__ e32,
                const float* __restrict__ gamma2, const float* __restrict__ beta2) {
    const int tid = threadIdx.x;
    const int w = tid >> 5, lane = tid & 31;
    const int gnode = blockIdx.x * 8 + w;     // 0 .. 39999
    const int b = (gnode >= NN) ? 1 : 0;
    const int i = gnode - b * NN;

    // edge layout detection (int64 high words are all zero)
    const bool is64 = ((e32[1] | e32[3] | e32[5] | e32[7] |
                        e32[9] | e32[11] | e32[13] | e32[15]) == 0);
    int myd = 0;
    if (lane < 8) {
        int e = i * DEG + lane;
        myd = is64 ? e32[4 * e + 2] : e32[2 * e + 1];
    }
    const int s = is64 ? e32[4 * (i * DEG)] : e32[2 * (i * DEG)];  // same addr -> broadcast

    const int ch = lane * 8;                 // 8 channels per lane
    const size_t rowq = (size_t)(b * NN + s) * 768 + ch;

    union U4 { uint4 u; __half2 h2[4]; };
    U4 qu; qu.u = *(const uint4*)(g_qkv + rowq);
    float2 qf[4];
    #pragma unroll
    for (int p = 0; p < 4; p++) qf[p] = __half22float2(qu.h2[p]);

    size_t rk[DEG];
    #pragma unroll
    for (int j = 0; j < DEG; j++) {
        int dj = __shfl_sync(0xffffffffu, myd, j);
        rk[j] = (size_t)(b * NN + dj) * 768 + 256 + ch;
    }

    // phase 1: all 8 k loads in flight, partial dots
    float pd[DEG];
    #pragma unroll
    for (int j = 0; j < DEG; j++) {
        U4 ku; ku.u = *(const uint4*)(g_qkv + rk[j]);
        float d = 0.f;
        #pragma unroll
        for (int p = 0; p < 4; p++) {
            float2 kf = __half22float2(ku.h2[p]);
            d += qf[p].x * kf.x + qf[p].y * kf.y;
        }
        pd[j] = d;
    }
    // phase 2: reduce within 4-lane head groups (head = 32ch = 4 lanes), exp
    float wj[DEG], den = 0.f;
    #pragma unroll
    for (int j = 0; j < DEG; j++) {
        float p = pd[j];
        p += __shfl_xor_sync(0xffffffffu, p, 1);
        p += __shfl_xor_sync(0xffffffffu, p, 2);
        wj[j] = __expf(p * INV_SQRT_DH);
        den += wj[j];
    }
    // phase 3: v pass
    float num[8];
    #pragma unroll
    for (int q = 0; q < 8; q++) num[q] = 0.f;
    #pragma unroll
    for (int j = 0; j < DEG; j++) {
        U4 vu; vu.u = *(const uint4*)(g_qkv + rk[j] + 256);
        #pragma unroll
        for (int p = 0; p < 4; p++) {
            float2 vf = __half22float2(vu.h2[p]);
            num[2*p]   += wj[j] * vf.x;
            num[2*p+1] += wj[j] * vf.y;
        }
    }
    const float inv = 1.f / den;

    // residual: xn = hi + lo
    const size_t off = (size_t)(b * NN + s) * DD + ch;
    U4 xh, xl;
    xh.u = *(const uint4*)(g_xnh + off);
    xl.u = *(const uint4*)(g_xnl + off);
    float c[8];
    #pragma unroll
    for (int p = 0; p < 4; p++) {
        float2 h2 = __half22float2(xh.h2[p]);
        float2 l2 = __half22float2(xl.h2[p]);
        c[2*p]   = h2.x + l2.x + num[2*p]   * inv;
        c[2*p+1] = h2.y + l2.y + num[2*p+1] * inv;
    }

    // LayerNorm over 256 channels within the warp
    float ls = 0.f;
    #pragma unroll
    for (int q = 0; q < 8; q++) ls += c[q];
    #pragma unroll
    for (int o = 16; o; o >>= 1) ls += __shfl_xor_sync(0xffffffffu, ls, o);
    const float mu = ls * (1.f / 256.f);

    float d[8], lv = 0.f;
    #pragma unroll
    for (int q = 0; q < 8; q++) { d[q] = c[q] - mu; lv += d[q] * d[q]; }
    #pragma unroll
    for (int o = 16; o; o >>= 1) lv += __shfl_xor_sync(0xffffffffu, lv, o);
    const float rs = rsqrtf(lv * (1.f / 256.f) + LN_EPS);

    float4 gm0 = *(const float4*)(gamma2 + ch);
    float4 gm1 = *(const float4*)(gamma2 + ch + 4);
    float4 bt0 = *(const float4*)(beta2 + ch);
    float4 bt1 = *(const float4*)(beta2 + ch + 4);
    float tv[8];
    tv[0] = d[0] * rs * gm0.x + bt0.x;  tv[1] = d[1] * rs * gm0.y + bt0.y;
    tv[2] = d[2] * rs * gm0.z + bt0.z;  tv[3] = d[3] * rs * gm0.w + bt0.w;
    tv[4] = d[4] * rs * gm1.x + bt1.x;  tv[5] = d[5] * rs * gm1.y + bt1.y;
    tv[6] = d[6] * rs * gm1.z + bt1.z;  tv[7] = d[7] * rs * gm1.w + bt1.w;

    *(float4*)(g_concat + off)     = make_float4(c[0], c[1], c[2], c[3]);
    *(float4*)(g_concat + off + 4) = make_float4(c[4], c[5], c[6], c[7]);

    U4 oh;
    #pragma unroll
    for (int p = 0; p < 4; p++)
        oh.h2[p] = __floats2half2_rn(tv[2*p], tv[2*p+1]);
    *(uint4*)(g_th + off) = oh.u;
}

// ---------------- launch ----------------
extern "C" void kernel_launch(void* const* d_in, const int* in_sizes, int n_in,
                              void* d_out, int out_size) {
    const float* x      = (const float*)d_in[0];
    const int*   edges  = (const int*)d_in[1];
    const float* wq     = (const float*)d_in[2];
    const float* bq     = (const float*)d_in[3];
    const float* wk     = (const float*)d_in[4];
    const float* bk     = (const float*)d_in[5];
    const float* wv     = (const float*)d_in[6];
    const float* bv     = (const float*)d_in[7];
    const float* wo     = (const float*)d_in[8];
    const float* bo     = (const float*)d_in[9];
    const float* gamma1 = (const float*)d_in[10];
    const float* beta1  = (const float*)d_in[11];
    const float* gamma2 = (const float*)d_in[12];
    const float* beta2  = (const float*)d_in[13];
    float* out = (float*)d_out;

    __half *xnh, *th, *wT, *woT, *qkv_p;
    float *bias_p, *concat_p;
    cudaGetSymbolAddress((void**)&xnh,  g_xnh);
    cudaGetSymbolAddress((void**)&th,   g_th);
    cudaGetSymbolAddress((void**)&wT,   g_wqkvT);
    cudaGetSymbolAddress((void**)&woT,  g_woT);
    cudaGetSymbolAddress((void**)&qkv_p,    g_qkv);
    cudaGetSymbolAddress((void**)&bias_p,   g_bias);
    cudaGetSymbolAddress((void**)&concat_p, g_concat);

    cudaFuncSetAttribute(hmma_gemm_kernel<false>,
        cudaFuncAttributeMaxDynamicSharedMemorySize, SMEM_TOTAL_GEMM);
    cudaFuncSetAttribute(hmma_gemm_kernel<true>,
        cudaFuncAttributeMaxDynamicSharedMemorySize, SMEM_TOTAL_GEMM);

    // 0) pack fp16 weights
    pack_w_kernel<<<768, 256>>>(wq, wk, wv, wo, bq, bk, bv);
    // 1) LayerNorm1 -> fp16 hi/lo
    ln1_kernel<<<ROWS, 256>>>(x, gamma1, beta1);
    // 2) QKV projection: [40000 x 256] @ [256 x 768] -> fp16 qkv
    {
        dim3 grid(6, 48);     // 288 CTAs, 2/SM
        hmma_gemm_kernel<false><<<grid, 256, SMEM_TOTAL_GEMM>>>(
            xnh, wT, bias_p, nullptr, qkv_p, ROWS, 768);
    }
    // 3) attention + residual + LayerNorm2 (warp per node)
    attn_ln2_kernel<<<ROWS / 8, 256>>>(edges, gamma2, beta2);
    // 4) output projection + ReLU + residual -> fp32 out
    {
        dim3 grid(2, 144);    // 288 CTAs, 2/SM
        hmma_gemm_kernel<true><<<grid, 256, SMEM_TOTAL_GEMM>>>(
            th, woT, bo, concat_p, out, ROWS, 256);
    }
}

// round 7
// speedup vs baseline: 2.2320x; 1.2270x over previous
#include <cuda_runtime.h>
#include <cuda_fp16.h>
#include <cstdint>
#include <math.h>

// Problem constants (fixed by reference setup_inputs)
#define BB 2
#define NN 20000
#define DD 256
#define HH 8
#define DH 32
#define DEG 8
#define ROWS (BB*NN)          // 40000
#define PADROWS 40064         // padded to multiple of 128 for unguarded tile loads
#define LN_EPS 1e-3f
#define INV_SQRT_DH 0.17677669529663687f  // 1/sqrt(32)

// ---------------- scratch (device globals; no allocations allowed) ----------------
__device__ __half g_xnh[(size_t)PADROWS * DD];   // LN1 out hi (fp16) — GEMM A input
__device__ __half g_xnl[(size_t)PADROWS * DD];   // LN1 out lo (fp16) — residual accuracy only
__device__ __half g_th [(size_t)PADROWS * DD];   // LN2 out (fp16)
__device__ __half g_qkv[(size_t)ROWS * 3 * DD];  // q|k|v per row (fp16, 61MB, L2-resident)
__device__ float g_concat[(size_t)ROWS * DD];    // xn + attn (fp32)
__device__ float g_bias[768];                    // packed [bq|bk|bv]
__device__ __half g_wqkvT[768 * 256];            // W^T fp16 [n][k]
__device__ __half g_woT[256 * 256];              // wo^T fp16

// ---------------- PTX helpers (sm_80-era: valid on base sm_103 target) ----------------
__device__ __forceinline__ void cp_async16(uint32_t dst, const void* src) {
    asm volatile("cp.async.cg.shared.global [%0], [%1], 16;" :: "r"(dst), "l"(src));
}
#define CP_COMMIT() asm volatile("cp.async.commit_group;" ::: "memory")
#define CP_WAIT(n)  asm volatile("cp.async.wait_group %0;" :: "n"(n) : "memory")

__device__ __forceinline__ uint32_t smem_to_u32(const void* p) {
    uint32_t a;
    asm("{ .reg .u64 t; cvta.to.shared.u64 t, %1; cvt.u32.u64 %0, t; }" : "=r"(a) : "l"(p));
    return a;
}
__device__ __forceinline__ void ldsm4(uint32_t* r, uint32_t addr) {
    asm volatile("ldmatrix.sync.aligned.m8n8.x4.shared.b16 {%0,%1,%2,%3}, [%4];"
        : "=r"(r[0]), "=r"(r[1]), "=r"(r[2]), "=r"(r[3]) : "r"(addr));
}
__device__ __forceinline__ void mma16816(float* c, const uint32_t* a, const uint32_t* b) {
    asm volatile("mma.sync.aligned.m16n8k16.row.col.f32.f16.f16.f32 "
        "{%0,%1,%2,%3}, {%4,%5,%6,%7}, {%8,%9}, {%0,%1,%2,%3};"
        : "+f"(c[0]), "+f"(c[1]), "+f"(c[2]), "+f"(c[3])
        : "r"(a[0]), "r"(a[1]), "r"(a[2]), "r"(a[3]), "r"(b[0]), "r"(b[1]));
}

// ---------------- kernel 0: pack transposed fp16 weights + bias ----------------
__global__ void pack_w_kernel(const float* __restrict__ wq, const float* __restrict__ wk,
                              const float* __restrict__ wv, const float* __restrict__ wo,
                              const float* __restrict__ bq, const float* __restrict__ bk,
                              const float* __restrict__ bv) {
    int idx = blockIdx.x * 256 + threadIdx.x;   // 0 .. 196607
    int n = idx / 256, k = idx % 256;
    float w = (n < 256) ? wq[k * 256 + n]
            : (n < 512) ? wk[k * 256 + (n - 256)]
                        : wv[k * 256 + (n - 512)];
    g_wqkvT[idx] = __float2half(w);
    if (idx < 65536) g_woT[idx] = __float2half(wo[k * 256 + n]);
    if (idx < 768) {
        g_bias[idx] = (idx < 256) ? bq[idx] : (idx < 512) ? bk[idx - 256] : bv[idx - 512];
    }
}

// ---------------- kernel 1: LayerNorm1, warp-per-row -> fp16 hi/lo ----------------
__global__ void __launch_bounds__(256)
ln1_kernel(const float* __restrict__ x, const float* __restrict__ g,
           const float* __restrict__ bt) {
    const int tid = threadIdx.x;
    const int w = tid >> 5, lane = tid & 31;
    const int row = blockIdx.x * 8 + w;
    const size_t off = (size_t)row * DD + lane * 8;

    float4 a = *(const float4*)(x + off);
    float4 b4 = *(const float4*)(x + off + 4);
    float v[8] = {a.x, a.y, a.z, a.w, b4.x, b4.y, b4.z, b4.w};

    float s = 0.f;
    #pragma unroll
    for (int q = 0; q < 8; q++) s += v[q];
    #pragma unroll
    for (int o = 16; o; o >>= 1) s += __shfl_xor_sync(0xffffffffu, s, o);
    const float mu = s * (1.f / 256.f);

    float d[8], lv = 0.f;
    #pragma unroll
    for (int q = 0; q < 8; q++) { d[q] = v[q] - mu; lv += d[q] * d[q]; }
    #pragma unroll
    for (int o = 16; o; o >>= 1) lv += __shfl_xor_sync(0xffffffffu, lv, o);
    const float rs = rsqrtf(lv * (1.f / 256.f) + LN_EPS);

    float4 gm0 = *(const float4*)(g + lane * 8);
    float4 gm1 = *(const float4*)(g + lane * 8 + 4);
    float4 bt0 = *(const float4*)(bt + lane * 8);
    float4 bt1 = *(const float4*)(bt + lane * 8 + 4);
    float y[8];
    y[0] = d[0] * rs * gm0.x + bt0.x;  y[1] = d[1] * rs * gm0.y + bt0.y;
    y[2] = d[2] * rs * gm0.z + bt0.z;  y[3] = d[3] * rs * gm0.w + bt0.w;
    y[4] = d[4] * rs * gm1.x + bt1.x;  y[5] = d[5] * rs * gm1.y + bt1.y;
    y[6] = d[6] * rs * gm1.z + bt1.z;  y[7] = d[7] * rs * gm1.w + bt1.w;

    union U4 { uint4 u; __half2 h2[4]; } oh, ol;
    #pragma unroll
    for (int p = 0; p < 4; p++) {
        __half h0 = __float2half(y[2*p]);
        __half h1 = __float2half(y[2*p+1]);
        oh.h2[p] = __halves2half2(h0, h1);
        ol.h2[p] = __halves2half2(__float2half(y[2*p]   - __half2float(h0)),
                                  __float2half(y[2*p+1] - __half2float(h1)));
    }
    *(uint4*)(g_xnh + off) = oh.u;
    *(uint4*)(g_xnl + off) = ol.u;
}

// ---------------- HMMA GEMM (single-term fp16, 4-stage cp.async ring) ----------------
// C[M x Ncols] = A[M x 256] @ B^T + bias; both operands fp16.
// B (N-major BT[n][k]) persistent in SMEM for full K=256 (66KB).
// A: BK=32 chunks in a 4-stage ring; ONE __syncthreads per chunk (the post-wait
// barrier proves all warps finished chunk c-1 before buf (c+3)%4 == (c-1)%4 is reused).
#define BPITCH 528            // 512B data + 16B pad
#define APITCH 80             // 64B data + 16B pad
#define OFF_A  (128 * BPITCH)             // 67584
#define A_BUF  (128 * APITCH)             // 10240
#define SMEM_TOTAL_GEMM (OFF_A + 4 * A_BUF)   // 108544 -> 2 CTAs/SM

__device__ __forceinline__ void issue_A_chunk(uint32_t sb, int buf,
        const __half* __restrict__ A, int row0, int kc, int tid) {
    #pragma unroll
    for (int rep = 0; rep < 2; rep++) {
        int idx = rep * 256 + tid;          // 0..511
        int row = idx >> 2, cc = idx & 3;
        uint32_t dst = sb + OFF_A + buf * A_BUF + row * APITCH + cc * 16;
        cp_async16(dst, A + (size_t)(row0 + row) * 256 + kc * 32 + cc * 8);
    }
}

template<bool FUSE_OUT>
__global__ void __launch_bounds__(256, 2)
hmma_gemm_kernel(const __half* __restrict__ A,
                 const __half* __restrict__ BT,
                 const float* __restrict__ bias, const float* __restrict__ add,
                 void* __restrict__ Cout, int M, int Ncols) {
    extern __shared__ __align__(1024) char smem[];
    const uint32_t sb = smem_to_u32(smem);
    const int tid = threadIdx.x;
    const int lane = tid & 31;
    const int wid = tid >> 5;
    const int wm = wid & 1;       // M dir, 64 rows each
    const int wn = wid >> 1;      // N dir, 32 cols each
    const int n0 = blockIdx.x * 128;

    // ---- load persistent B (fp16, full K); rides chunk 0's commit group ----
    #pragma unroll
    for (int j = 0; j < 16; j++) {
        int idx = j * 256 + tid;            // 0..4095
        int row = idx >> 5, cc = idx & 31;
        uint32_t dst = sb + row * BPITCH + cc * 16;
        cp_async16(dst, BT + (size_t)(n0 + row) * 256 + cc * 8);
    }

    const uint32_t a_lane_off = (uint32_t)((lane & 15) * APITCH + (lane >> 4) * 16);
    const int b_row = wn * 32 + ((lane >> 4) << 3) + (lane & 7);
    const uint32_t b_lane_off = (uint32_t)(b_row * BPITCH + ((lane >> 3) & 1) * 16);

    const int ntiles = (M + 127) >> 7;

    for (int mt = blockIdx.y; mt < ntiles; mt += gridDim.y) {
        const int row0 = mt << 7;

        float acc[4][4][4];
        #pragma unroll
        for (int i = 0; i < 4; i++)
            #pragma unroll
            for (int j = 0; j < 4; j++)
                #pragma unroll
                for (int r = 0; r < 4; r++) acc[i][j][r] = 0.f;

        // prologue: 3 chunks in flight
        #pragma unroll
        for (int p = 0; p < 3; p++) {
            issue_A_chunk(sb, p, A, row0, p, tid);
            CP_COMMIT();
        }

        #pragma unroll 1
        for (int c = 0; c < 8; c++) {
            if (c < 6) CP_WAIT(2);
            else if (c == 6) CP_WAIT(1);
            else CP_WAIT(0);
            __syncthreads();                 // single barrier per chunk
            if (c < 5) {
                issue_A_chunk(sb, (c + 3) & 3, A, row0, c + 3, tid);
                CP_COMMIT();
            }

            const uint32_t abase = sb + OFF_A + (c & 3) * A_BUF + (wm * 64) * APITCH + a_lane_off;
            #pragma unroll
            for (int q = 0; q < 2; q++) {
                uint32_t ah[4][4], bh[2][4];
                #pragma unroll
                for (int mf = 0; mf < 4; mf++)
                    ldsm4(ah[mf], abase + mf * 16 * APITCH + q * 32);
                const int kk = c * 2 + q;
                const uint32_t bbase = sb + b_lane_off + kk * 32;
                #pragma unroll
                for (int p = 0; p < 2; p++) ldsm4(bh[p], bbase + p * 16 * BPITCH);
                #pragma unroll
                for (int mf = 0; mf < 4; mf++) {
                    #pragma unroll
                    for (int nf = 0; nf < 4; nf++) {
                        const uint32_t* bp = &bh[nf >> 1][(nf & 1) * 2];
                        mma16816(acc[mf][nf], ah[mf], bp);
                    }
                }
            }
        }

        // ---- epilogue ----
        const int colb = n0 + wn * 32 + (lane & 3) * 2;
        #pragma unroll
        for (int mf = 0; mf < 4; mf++) {
            const int r1 = row0 + wm * 64 + mf * 16 + (lane >> 2);
            const int r2 = r1 + 8;
            #pragma unroll
            for (int nf = 0; nf < 4; nf++) {
                const int gc = colb + nf * 8;
                float2 b2 = *(const float2*)(bias + gc);
                float2 v1 = make_float2(acc[mf][nf][0] + b2.x, acc[mf][nf][1] + b2.y);
                float2 v2 = make_float2(acc[mf][nf][2] + b2.x, acc[mf][nf][3] + b2.y);
                if (FUSE_OUT) {
                    float* C = (float*)Cout;
                    if (r1 < M) {
                        float2 a1 = *(const float2*)(add + (size_t)r1 * Ncols + gc);
                        v1.x = fmaxf(v1.x, 0.f) + a1.x;
                        v1.y = fmaxf(v1.y, 0.f) + a1.y;
                        *(float2*)(C + (size_t)r1 * Ncols + gc) = v1;
                    }
                    if (r2 < M) {
                        float2 a2 = *(const float2*)(add + (size_t)r2 * Ncols + gc);
                        v2.x = fmaxf(v2.x, 0.f) + a2.x;
                        v2.y = fmaxf(v2.y, 0.f) + a2.y;
                        *(float2*)(C + (size_t)r2 * Ncols + gc) = v2;
                    }
                } else {
                    __half* C = (__half*)Cout;
                    if (r1 < M)
                        *(__half2*)(C + (size_t)r1 * Ncols + gc) = __floats2half2_rn(v1.x, v1.y);
                    if (r2 < M)
                        *(__half2*)(C + (size_t)r2 * Ncols + gc) = __floats2half2_rn(v2.x, v2.y);
                }
            }
        }
        __syncthreads();   // all warps done before next tile's prologue reuses bufs
    }
}

// ---------------- kernel 3: attention + residual + LayerNorm2 ----------------
// One WARP per node (8 nodes/block). Each lane owns 8 channels (16B fp16 loads).
// 32-bit qkv offsets (max 30.7M elems) for register diet; occupancy target 5 blocks/SM.
__global__ void __launch_bounds__(256, 5)
attn_ln2_kernel(const int* __restrict__ e32,
                const float* __restrict__ gamma2, const float* __restrict__ beta2) {
    const int tid = threadIdx.x;
    const int w = tid >> 5, lane = tid & 31;
    const int gnode = blockIdx.x * 8 + w;     // 0 .. 39999
    const int b = (gnode >= NN) ? 1 : 0;
    const int i = gnode - b * NN;

    // edge layout detection (int64 high words are all zero)
    const bool is64 = ((e32[1] | e32[3] | e32[5] | e32[7] |
                        e32[9] | e32[11] | e32[13] | e32[15]) == 0);
    int myd = 0;
    if (lane < 8) {
        int e = i * DEG + lane;
        myd = is64 ? e32[4 * e + 2] : e32[2 * e + 1];
    }
    const int s = is64 ? e32[4 * (i * DEG)] : e32[2 * (i * DEG)];  // same addr -> broadcast

    const int ch = lane * 8;                 // 8 channels per lane
    const uint32_t rowq = (uint32_t)(b * NN + s) * 768 + ch;

    union U4 { uint4 u; __half2 h2[4]; };
    U4 qu; qu.u = *(const uint4*)(g_qkv + rowq);
    float2 qf[4];
    #pragma unroll
    for (int p = 0; p < 4; p++) qf[p] = __half22float2(qu.h2[p]);

    uint32_t rk[DEG];
    #pragma unroll
    for (int j = 0; j < DEG; j++) {
        int dj = __shfl_sync(0xffffffffu, myd, j);
        rk[j] = (uint32_t)(b * NN + dj) * 768 + 256 + ch;
    }

    // phase 1: all 8 k loads in flight, partial dots
    float pd[DEG];
    #pragma unroll
    for (int j = 0; j < DEG; j++) {
        U4 ku; ku.u = *(const uint4*)(g_qkv + rk[j]);
        float d = 0.f;
        #pragma unroll
        for (int p = 0; p < 4; p++) {
            float2 kf = __half22float2(ku.h2[p]);
            d += qf[p].x * kf.x + qf[p].y * kf.y;
        }
        pd[j] = d;
    }
    // phase 2: reduce within 4-lane head groups (head = 32ch = 4 lanes), exp
    float wj[DEG], den = 0.f;
    #pragma unroll
    for (int j = 0; j < DEG; j++) {
        float p = pd[j];
        p += __shfl_xor_sync(0xffffffffu, p, 1);
        p += __shfl_xor_sync(0xffffffffu, p, 2);
        wj[j] = __expf(p * INV_SQRT_DH);
        den += wj[j];
    }
    // phase 3: v pass
    float num[8];
    #pragma unroll
    for (int q = 0; q < 8; q++) num[q] = 0.f;
    #pragma unroll
    for (int j = 0; j < DEG; j++) {
        U4 vu; vu.u = *(const uint4*)(g_qkv + rk[j] + 256);
        #pragma unroll
        for (int p = 0; p < 4; p++) {
            float2 vf = __half22float2(vu.h2[p]);
            num[2*p]   += wj[j] * vf.x;
            num[2*p+1] += wj[j] * vf.y;
        }
    }
    const float inv = 1.f / den;

    // residual: xn = hi + lo
    const uint32_t off = (uint32_t)(b * NN + s) * DD + ch;
    U4 xh, xl;
    xh.u = *(const uint4*)(g_xnh + off);
    xl.u = *(const uint4*)(g_xnl + off);
    float c[8];
    #pragma unroll
    for (int p = 0; p < 4; p++) {
        float2 h2 = __half22float2(xh.h2[p]);
        float2 l2 = __half22float2(xl.h2[p]);
        c[2*p]   = h2.x + l2.x + num[2*p]   * inv;
        c[2*p+1] = h2.y + l2.y + num[2*p+1] * inv;
    }

    // LayerNorm over 256 channels within the warp
    float ls = 0.f;
    #pragma unroll
    for (int q = 0; q < 8; q++) ls += c[q];
    #pragma unroll
    for (int o = 16; o; o >>= 1) ls += __shfl_xor_sync(0xffffffffu, ls, o);
    const float mu = ls * (1.f / 256.f);

    float d[8], lv = 0.f;
    #pragma unroll
    for (int q = 0; q < 8; q++) { d[q] = c[q] - mu; lv += d[q] * d[q]; }
    #pragma unroll
    for (int o = 16; o; o >>= 1) lv += __shfl_xor_sync(0xffffffffu, lv, o);
    const float rs = rsqrtf(lv * (1.f / 256.f) + LN_EPS);

    float4 gm0 = *(const float4*)(gamma2 + ch);
    float4 gm1 = *(const float4*)(gamma2 + ch + 4);
    float4 bt0 = *(const float4*)(beta2 + ch);
    float4 bt1 = *(const float4*)(beta2 + ch + 4);
    float tv[8];
    tv[0] = d[0] * rs * gm0.x + bt0.x;  tv[1] = d[1] * rs * gm0.y + bt0.y;
    tv[2] = d[2] * rs * gm0.z + bt0.z;  tv[3] = d[3] * rs * gm0.w + bt0.w;
    tv[4] = d[4] * rs * gm1.x + bt1.x;  tv[5] = d[5] * rs * gm1.y + bt1.y;
    tv[6] = d[6] * rs * gm1.z + bt1.z;  tv[7] = d[7] * rs * gm1.w + bt1.w;

    *(float4*)(g_concat + off)     = make_float4(c[0], c[1], c[2], c[3]);
    *(float4*)(g_concat + off + 4) = make_float4(c[4], c[5], c[6], c[7]);

    U4 oh;
    #pragma unroll
    for (int p = 0; p < 4; p++)
        oh.h2[p] = __floats2half2_rn(tv[2*p], tv[2*p+1]);
    *(uint4*)(g_th + off) = oh.u;
}

// ---------------- launch ----------------
extern "C" void kernel_launch(void* const* d_in, const int* in_sizes, int n_in,
                              void* d_out, int out_size) {
    const float* x      = (const float*)d_in[0];
    const int*   edges  = (const int*)d_in[1];
    const float* wq     = (const float*)d_in[2];
    const float* bq     = (const float*)d_in[3];
    const float* wk     = (const float*)d_in[4];
    const float* bk     = (const float*)d_in[5];
    const float* wv     = (const float*)d_in[6];
    const float* bv     = (const float*)d_in[7];
    const float* wo     = (const float*)d_in[8];
    const float* bo     = (const float*)d_in[9];
    const float* gamma1 = (const float*)d_in[10];
    const float* beta1  = (const float*)d_in[11];
    const float* gamma2 = (const float*)d_in[12];
    const float* beta2  = (const float*)d_in[13];
    float* out = (float*)d_out;

    __half *xnh, *th, *wT, *woT, *qkv_p;
    float *bias_p, *concat_p;
    cudaGetSymbolAddress((void**)&xnh,  g_xnh);
    cudaGetSymbolAddress((void**)&th,   g_th);
    cudaGetSymbolAddress((void**)&wT,   g_wqkvT);
    cudaGetSymbolAddress((void**)&woT,  g_woT);
    cudaGetSymbolAddress((void**)&qkv_p,    g_qkv);
    cudaGetSymbolAddress((void**)&bias_p,   g_bias);
    cudaGetSymbolAddress((void**)&concat_p, g_concat);

    cudaFuncSetAttribute(hmma_gemm_kernel<false>,
        cudaFuncAttributeMaxDynamicSharedMemorySize, SMEM_TOTAL_GEMM);
    cudaFuncSetAttribute(hmma_gemm_kernel<true>,
        cudaFuncAttributeMaxDynamicSharedMemorySize, SMEM_TOTAL_GEMM);

    // 0) pack fp16 weights
    pack_w_kernel<<<768, 256>>>(wq, wk, wv, wo, bq, bk, bv);
    // 1) LayerNorm1 (warp per row) -> fp16 hi/lo
    ln1_kernel<<<ROWS / 8, 256>>>(x, gamma1, beta1);
    // 2) QKV projection: [40000 x 256] @ [256 x 768] -> fp16 qkv
    {
        dim3 grid(6, 49);     // 294 CTAs <= 296 resident at 2/SM
        hmma_gemm_kernel<false><<<grid, 256, SMEM_TOTAL_GEMM>>>(
            xnh, wT, bias_p, nullptr, qkv_p, ROWS, 768);
    }
    // 3) attention + residual + LayerNorm2 (warp per node)
    attn_ln2_kernel<<<ROWS / 8, 256>>>(edges, gamma2, beta2);
    // 4) output projection + ReLU + residual -> fp32 out
    {
        dim3 grid(2, 148);    // 296 CTAs, exactly 2/SM
        hmma_gemm_kernel<true><<<grid, 256, SMEM_TOTAL_GEMM>>>(
            th, woT, bo, concat_p, out, ROWS, 256);
    }
}

// round 8
// speedup vs baseline: 2.3155x; 1.0374x over previous
#include <cuda_runtime.h>
#include <cuda_fp16.h>
#include <cstdint>
#include <math.h>

// Problem constants (fixed by reference setup_inputs)
#define BB 2
#define NN 20000
#define DD 256
#define HH 8
#define DH 32
#define DEG 8
#define ROWS (BB*NN)          // 40000
#define PADROWS 40064         // padded to multiple of 128 for unguarded tile loads
#define LN_EPS 1e-3f
#define INV_SQRT_DH 0.17677669529663687f  // 1/sqrt(32)

// ---------------- scratch (device globals; no allocations allowed) ----------------
__device__ __half g_xnh[(size_t)PADROWS * DD];   // LN1 out (fp16) — GEMM A + residual
__device__ __half g_th [(size_t)PADROWS * DD];   // LN2 out (fp16)
__device__ __half g_q  [(size_t)ROWS * DD];      // q rows (sequential access, 20MB)
__device__ __half g_kv [(size_t)ROWS * 2 * DD];  // k|v adjacent per row (gather set, 41MB)
__device__ float g_concat[(size_t)ROWS * DD];    // xn + attn (fp32)
__device__ float g_bias[768];                    // packed [bq|bk|bv]
__device__ __half g_wqkvT[768 * 256];            // W^T fp16 [n][k]
__device__ __half g_woT[256 * 256];              // wo^T fp16

// ---------------- PTX helpers (sm_80-era: valid on base sm_103 target) ----------------
__device__ __forceinline__ void cp_async16(uint32_t dst, const void* src) {
    asm volatile("cp.async.cg.shared.global [%0], [%1], 16;" :: "r"(dst), "l"(src));
}
#define CP_COMMIT() asm volatile("cp.async.commit_group;" ::: "memory")
#define CP_WAIT(n)  asm volatile("cp.async.wait_group %0;" :: "n"(n) : "memory")

__device__ __forceinline__ uint32_t smem_to_u32(const void* p) {
    uint32_t a;
    asm("{ .reg .u64 t; cvta.to.shared.u64 t, %1; cvt.u32.u64 %0, t; }" : "=r"(a) : "l"(p));
    return a;
}
__device__ __forceinline__ void ldsm4(uint32_t* r, uint32_t addr) {
    asm volatile("ldmatrix.sync.aligned.m8n8.x4.shared.b16 {%0,%1,%2,%3}, [%4];"
        : "=r"(r[0]), "=r"(r[1]), "=r"(r[2]), "=r"(r[3]) : "r"(addr));
}
__device__ __forceinline__ void mma16816(float* c, const uint32_t* a, const uint32_t* b) {
    asm volatile("mma.sync.aligned.m16n8k16.row.col.f32.f16.f16.f32 "
        "{%0,%1,%2,%3}, {%4,%5,%6,%7}, {%8,%9}, {%0,%1,%2,%3};"
        : "+f"(c[0]), "+f"(c[1]), "+f"(c[2]), "+f"(c[3])
        : "r"(a[0]), "r"(a[1]), "r"(a[2]), "r"(a[3]), "r"(b[0]), "r"(b[1]));
}

// ---------------- kernel 1: LayerNorm1 (warp/row) + weight packing fused ----------------
__global__ void __launch_bounds__(256)
ln1_pack_kernel(const float* __restrict__ x, const float* __restrict__ g,
                const float* __restrict__ bt,
                const float* __restrict__ wq, const float* __restrict__ wk,
                const float* __restrict__ wv, const float* __restrict__ wo,
                const float* __restrict__ bq, const float* __restrict__ bk,
                const float* __restrict__ bv) {
    const int tid = threadIdx.x;
    const int w = tid >> 5, lane = tid & 31;
    const int row = blockIdx.x * 8 + w;
    const size_t off = (size_t)row * DD + lane * 8;

    float4 a = *(const float4*)(x + off);
    float4 b4 = *(const float4*)(x + off + 4);
    float v[8] = {a.x, a.y, a.z, a.w, b4.x, b4.y, b4.z, b4.w};

    float s = 0.f;
    #pragma unroll
    for (int q = 0; q < 8; q++) s += v[q];
    #pragma unroll
    for (int o = 16; o; o >>= 1) s += __shfl_xor_sync(0xffffffffu, s, o);
    const float mu = s * (1.f / 256.f);

    float d[8], lv = 0.f;
    #pragma unroll
    for (int q = 0; q < 8; q++) { d[q] = v[q] - mu; lv += d[q] * d[q]; }
    #pragma unroll
    for (int o = 16; o; o >>= 1) lv += __shfl_xor_sync(0xffffffffu, lv, o);
    const float rs = rsqrtf(lv * (1.f / 256.f) + LN_EPS);

    float4 gm0 = *(const float4*)(g + lane * 8);
    float4 gm1 = *(const float4*)(g + lane * 8 + 4);
    float4 bt0 = *(const float4*)(bt + lane * 8);
    float4 bt1 = *(const float4*)(bt + lane * 8 + 4);
    float y[8];
    y[0] = d[0] * rs * gm0.x + bt0.x;  y[1] = d[1] * rs * gm0.y + bt0.y;
    y[2] = d[2] * rs * gm0.z + bt0.z;  y[3] = d[3] * rs * gm0.w + bt0.w;
    y[4] = d[4] * rs * gm1.x + bt1.x;  y[5] = d[5] * rs * gm1.y + bt1.y;
    y[6] = d[6] * rs * gm1.z + bt1.z;  y[7] = d[7] * rs * gm1.w + bt1.w;

    union U4 { uint4 u; __half2 h2[4]; } oh;
    #pragma unroll
    for (int p = 0; p < 4; p++)
        oh.h2[p] = __floats2half2_rn(y[2*p], y[2*p+1]);
    *(uint4*)(g_xnh + off) = oh.u;

    // ---- fused weight pack (blocks 0..767 only) ----
    if (blockIdx.x < 768) {
        int idx = blockIdx.x * 256 + tid;   // 0 .. 196607
        int n = idx / 256, k = idx % 256;
        float ww = (n < 256) ? wq[k * 256 + n]
                 : (n < 512) ? wk[k * 256 + (n - 256)]
                             : wv[k * 256 + (n - 512)];
        g_wqkvT[idx] = __float2half(ww);
        if (idx < 65536) g_woT[idx] = __float2half(wo[k * 256 + n]);
        if (idx < 768)
            g_bias[idx] = (idx < 256) ? bq[idx] : (idx < 512) ? bk[idx - 256] : bv[idx - 512];
    }
}

// ---------------- HMMA GEMM (single-term fp16, 4-stage cp.async ring) ----------------
// MODE 0 (QKV): epilogue routes fp16 output by column block: cols [0,256)->g_q
//   (pitch 256), cols [256,768)->g_kv (pitch 512, k|v adjacent per row).
// MODE 1 (WO):  fp32 out = relu(acc+bias) + add.
#define BPITCH 528            // 512B data + 16B pad
#define APITCH 80             // 64B data + 16B pad
#define OFF_A  (128 * BPITCH)             // 67584
#define A_BUF  (128 * APITCH)             // 10240
#define SMEM_TOTAL_GEMM (OFF_A + 4 * A_BUF)   // 108544 -> 2 CTAs/SM

__device__ __forceinline__ void issue_A_chunk(uint32_t sb, int buf,
        const __half* __restrict__ A, int row0, int kc, int tid) {
    #pragma unroll
    for (int rep = 0; rep < 2; rep++) {
        int idx = rep * 256 + tid;          // 0..511
        int row = idx >> 2, cc = idx & 3;
        uint32_t dst = sb + OFF_A + buf * A_BUF + row * APITCH + cc * 16;
        cp_async16(dst, A + (size_t)(row0 + row) * 256 + kc * 32 + cc * 8);
    }
}

template<int MODE>
__global__ void __launch_bounds__(256, 2)
hmma_gemm_kernel(const __half* __restrict__ A,
                 const __half* __restrict__ BT,
                 const float* __restrict__ bias, const float* __restrict__ add,
                 float* __restrict__ Cf, int M) {
    extern __shared__ __align__(1024) char smem[];
    const uint32_t sb = smem_to_u32(smem);
    const int tid = threadIdx.x;
    const int lane = tid & 31;
    const int wid = tid >> 5;
    const int wm = wid & 1;       // M dir, 64 rows each
    const int wn = wid >> 1;      // N dir, 32 cols each
    const int n0 = blockIdx.x * 128;

    // ---- load persistent B (fp16, full K) ----
    #pragma unroll
    for (int j = 0; j < 16; j++) {
        int idx = j * 256 + tid;            // 0..4095
        int row = idx >> 5, cc = idx & 31;
        uint32_t dst = sb + row * BPITCH + cc * 16;
        cp_async16(dst, BT + (size_t)(n0 + row) * 256 + cc * 8);
    }

    const uint32_t a_lane_off = (uint32_t)((lane & 15) * APITCH + (lane >> 4) * 16);
    const int b_row = wn * 32 + ((lane >> 4) << 3) + (lane & 7);
    const uint32_t b_lane_off = (uint32_t)(b_row * BPITCH + ((lane >> 3) & 1) * 16);

    // QKV output routing (CTA-uniform)
    __half* Ch = nullptr;
    int out_pitch = 256, out_c0 = n0;
    if (MODE == 0) {
        if (n0 < 256) { Ch = g_q;  out_pitch = 256; out_c0 = n0; }
        else          { Ch = g_kv; out_pitch = 512; out_c0 = n0 - 256; }
    }

    const int ntiles = (M + 127) >> 7;

    for (int mt = blockIdx.y; mt < ntiles; mt += gridDim.y) {
        const int row0 = mt << 7;

        float acc[4][4][4];
        #pragma unroll
        for (int i = 0; i < 4; i++)
            #pragma unroll
            for (int j = 0; j < 4; j++)
                #pragma unroll
                for (int r = 0; r < 4; r++) acc[i][j][r] = 0.f;

        // prologue: 3 chunks in flight
        #pragma unroll
        for (int p = 0; p < 3; p++) {
            issue_A_chunk(sb, p, A, row0, p, tid);
            CP_COMMIT();
        }

        #pragma unroll 1
        for (int c = 0; c < 8; c++) {
            if (c < 6) CP_WAIT(2);
            else if (c == 6) CP_WAIT(1);
            else CP_WAIT(0);
            __syncthreads();                 // single barrier per chunk
            if (c < 5) {
                issue_A_chunk(sb, (c + 3) & 3, A, row0, c + 3, tid);
                CP_COMMIT();
            }

            const uint32_t abase = sb + OFF_A + (c & 3) * A_BUF + (wm * 64) * APITCH + a_lane_off;
            #pragma unroll
            for (int q = 0; q < 2; q++) {
                uint32_t ah[4][4], bh[2][4];
                #pragma unroll
                for (int mf = 0; mf < 4; mf++)
                    ldsm4(ah[mf], abase + mf * 16 * APITCH + q * 32);
                const int kk = c * 2 + q;
                const uint32_t bbase = sb + b_lane_off + kk * 32;
                #pragma unroll
                for (int p = 0; p < 2; p++) ldsm4(bh[p], bbase + p * 16 * BPITCH);
                #pragma unroll
                for (int mf = 0; mf < 4; mf++) {
                    #pragma unroll
                    for (int nf = 0; nf < 4; nf++) {
                        const uint32_t* bp = &bh[nf >> 1][(nf & 1) * 2];
                        mma16816(acc[mf][nf], ah[mf], bp);
                    }
                }
            }
        }

        // ---- epilogue ----
        const int colw = wn * 32 + (lane & 3) * 2;        // within 128-col block
        #pragma unroll
        for (int mf = 0; mf < 4; mf++) {
            const int r1 = row0 + wm * 64 + mf * 16 + (lane >> 2);
            const int r2 = r1 + 8;
            #pragma unroll
            for (int nf = 0; nf < 4; nf++) {
                const int bcol = n0 + colw + nf * 8;       // bias index (orig col)
                float2 b2 = *(const float2*)(bias + bcol);
                float2 v1 = make_float2(acc[mf][nf][0] + b2.x, acc[mf][nf][1] + b2.y);
                float2 v2 = make_float2(acc[mf][nf][2] + b2.x, acc[mf][nf][3] + b2.y);
                if (MODE == 1) {
                    const int gc = bcol;
                    if (r1 < M) {
                        float2 a1 = *(const float2*)(add + (size_t)r1 * 256 + gc);
                        v1.x = fmaxf(v1.x, 0.f) + a1.x;
                        v1.y = fmaxf(v1.y, 0.f) + a1.y;
                        *(float2*)(Cf + (size_t)r1 * 256 + gc) = v1;
                    }
                    if (r2 < M) {
                        float2 a2 = *(const float2*)(add + (size_t)r2 * 256 + gc);
                        v2.x = fmaxf(v2.x, 0.f) + a2.x;
                        v2.y = fmaxf(v2.y, 0.f) + a2.y;
                        *(float2*)(Cf + (size_t)r2 * 256 + gc) = v2;
                    }
                } else {
                    const int gc = out_c0 + colw + nf * 8;
                    if (r1 < M)
                        *(__half2*)(Ch + (size_t)r1 * out_pitch + gc) = __floats2half2_rn(v1.x, v1.y);
                    if (r2 < M)
                        *(__half2*)(Ch + (size_t)r2 * out_pitch + gc) = __floats2half2_rn(v2.x, v2.y);
                }
            }
        }
        __syncthreads();   // all warps done before next tile's prologue reuses bufs
    }
}

// ---------------- kernel 3: attention + residual + LayerNorm2 ----------------
// One WARP per node. Gathers hit the compact g_kv (41MB); q/xn sequential.
__global__ void __launch_bounds__(256, 6)
attn_ln2_kernel(const int* __restrict__ e32,
                const float* __restrict__ gamma2, const float* __restrict__ beta2) {
    const int tid = threadIdx.x;
    const int w = tid >> 5, lane = tid & 31;
    const int gnode = blockIdx.x * 8 + w;     // 0 .. 39999
    const int b = (gnode >= NN) ? 1 : 0;
    const int i = gnode - b * NN;

    // edge layout detection (int64 high words are all zero)
    const bool is64 = ((e32[1] | e32[3] | e32[5] | e32[7] |
                        e32[9] | e32[11] | e32[13] | e32[15]) == 0);
    int myd = 0;
    if (lane < 8) {
        int e = i * DEG + lane;
        myd = is64 ? e32[4 * e + 2] : e32[2 * e + 1];
    }
    const int s = is64 ? e32[4 * (i * DEG)] : e32[2 * (i * DEG)];  // same addr -> broadcast

    const int ch = lane * 8;                 // 8 channels per lane
    const uint32_t rowq = (uint32_t)(b * NN + s) * 256 + ch;

    union U4 { uint4 u; __half2 h2[4]; };
    U4 qu; qu.u = *(const uint4*)(g_q + rowq);
    float2 qf[4];
    #pragma unroll
    for (int p = 0; p < 4; p++) qf[p] = __half22float2(qu.h2[p]);

    uint32_t rk[DEG];
    #pragma unroll
    for (int j = 0; j < DEG; j++) {
        int dj = __shfl_sync(0xffffffffu, myd, j);
        rk[j] = (uint32_t)(b * NN + dj) * 512 + ch;   // k at +0, v at +256
    }

    // phase 1: all 8 k loads in flight, partial dots
    float pd[DEG];
    #pragma unroll
    for (int j = 0; j < DEG; j++) {
        U4 ku; ku.u = *(const uint4*)(g_kv + rk[j]);
        float d = 0.f;
        #pragma unroll
        for (int p = 0; p < 4; p++) {
            float2 kf = __half22float2(ku.h2[p]);
            d += qf[p].x * kf.x + qf[p].y * kf.y;
        }
        pd[j] = d;
    }
    // phase 2: reduce within 4-lane head groups (head = 32ch = 4 lanes), exp
    float wj[DEG], den = 0.f;
    #pragma unroll
    for (int j = 0; j < DEG; j++) {
        float p = pd[j];
        p += __shfl_xor_sync(0xffffffffu, p, 1);
        p += __shfl_xor_sync(0xffffffffu, p, 2);
        wj[j] = __expf(p * INV_SQRT_DH);
        den += wj[j];
    }
    // phase 3: v pass
    float num[8];
    #pragma unroll
    for (int q = 0; q < 8; q++) num[q] = 0.f;
    #pragma unroll
    for (int j = 0; j < DEG; j++) {
        U4 vu; vu.u = *(const uint4*)(g_kv + rk[j] + 256);
        #pragma unroll
        for (int p = 0; p < 4; p++) {
            float2 vf = __half22float2(vu.h2[p]);
            num[2*p]   += wj[j] * vf.x;
            num[2*p+1] += wj[j] * vf.y;
        }
    }
    const float inv = 1.f / den;

    // residual: xn (fp16)
    const uint32_t off = (uint32_t)(b * NN + s) * DD + ch;
    U4 xh;
    xh.u = *(const uint4*)(g_xnh + off);
    float c[8];
    #pragma unroll
    for (int p = 0; p < 4; p++) {
        float2 h2 = __half22float2(xh.h2[p]);
        c[2*p]   = h2.x + num[2*p]   * inv;
        c[2*p+1] = h2.y + num[2*p+1] * inv;
    }

    // LayerNorm over 256 channels within the warp
    float ls = 0.f;
    #pragma unroll
    for (int q = 0; q < 8; q++) ls += c[q];
    #pragma unroll
    for (int o = 16; o; o >>= 1) ls += __shfl_xor_sync(0xffffffffu, ls, o);
    const float mu = ls * (1.f / 256.f);

    float d[8], lv = 0.f;
    #pragma unroll
    for (int q = 0; q < 8; q++) { d[q] = c[q] - mu; lv += d[q] * d[q]; }
    #pragma unroll
    for (int o = 16; o; o >>= 1) lv += __shfl_xor_sync(0xffffffffu, lv, o);
    const float rs = rsqrtf(lv * (1.f / 256.f) + LN_EPS);

    float4 gm0 = *(const float4*)(gamma2 + ch);
    float4 gm1 = *(const float4*)(gamma2 + ch + 4);
    float4 bt0 = *(const float4*)(beta2 + ch);
    float4 bt1 = *(const float4*)(beta2 + ch + 4);
    float tv[8];
    tv[0] = d[0] * rs * gm0.x + bt0.x;  tv[1] = d[1] * rs * gm0.y + bt0.y;
    tv[2] = d[2] * rs * gm0.z + bt0.z;  tv[3] = d[3] * rs * gm0.w + bt0.w;
    tv[4] = d[4] * rs * gm1.x + bt1.x;  tv[5] = d[5] * rs * gm1.y + bt1.y;
    tv[6] = d[6] * rs * gm1.z + bt1.z;  tv[7] = d[7] * rs * gm1.w + bt1.w;

    *(float4*)(g_concat + off)     = make_float4(c[0], c[1], c[2], c[3]);
    *(float4*)(g_concat + off + 4) = make_float4(c[4], c[5], c[6], c[7]);

    U4 oh;
    #pragma unroll
    for (int p = 0; p < 4; p++)
        oh.h2[p] = __floats2half2_rn(tv[2*p], tv[2*p+1]);
    *(uint4*)(g_th + off) = oh.u;
}

// ---------------- launch ----------------
extern "C" void kernel_launch(void* const* d_in, const int* in_sizes, int n_in,
                              void* d_out, int out_size) {
    const float* x      = (const float*)d_in[0];
    const int*   edges  = (const int*)d_in[1];
    const float* wq     = (const float*)d_in[2];
    const float* bq     = (const float*)d_in[3];
    const float* wk     = (const float*)d_in[4];
    const float* bk     = (const float*)d_in[5];
    const float* wv     = (const float*)d_in[6];
    const float* bv     = (const float*)d_in[7];
    const float* wo     = (const float*)d_in[8];
    const float* bo     = (const float*)d_in[9];
    const float* gamma1 = (const float*)d_in[10];
    const float* beta1  = (const float*)d_in[11];
    const float* gamma2 = (const float*)d_in[12];
    const float* beta2  = (const float*)d_in[13];
    float* out = (float*)d_out;

    __half *xnh, *th, *wT, *woT;
    float *bias_p, *concat_p;
    cudaGetSymbolAddress((void**)&xnh,  g_xnh);
    cudaGetSymbolAddress((void**)&th,   g_th);
    cudaGetSymbolAddress((void**)&wT,   g_wqkvT);
    cudaGetSymbolAddress((void**)&woT,  g_woT);
    cudaGetSymbolAddress((void**)&bias_p,   g_bias);
    cudaGetSymbolAddress((void**)&concat_p, g_concat);

    cudaFuncSetAttribute(hmma_gemm_kernel<0>,
        cudaFuncAttributeMaxDynamicSharedMemorySize, SMEM_TOTAL_GEMM);
    cudaFuncSetAttribute(hmma_gemm_kernel<1>,
        cudaFuncAttributeMaxDynamicSharedMemorySize, SMEM_TOTAL_GEMM);

    // 1) LayerNorm1 (warp per row) -> fp16, with fused weight packing
    ln1_pack_kernel<<<ROWS / 8, 256>>>(x, gamma1, beta1, wq, wk, wv, wo, bq, bk, bv);
    // 2) QKV projection: [40000 x 256] @ [256 x 768] -> g_q / g_kv (fp16)
    {
        dim3 grid(6, 49);     // 294 CTAs <= 296 resident at 2/SM
        hmma_gemm_kernel<0><<<grid, 256, SMEM_TOTAL_GEMM>>>(
            xnh, wT, bias_p, nullptr, nullptr, ROWS);
    }
    // 3) attention + residual + LayerNorm2 (warp per node)
    attn_ln2_kernel<<<ROWS / 8, 256>>>(edges, gamma2, beta2);
    // 4) output projection + ReLU + residual -> fp32 out (bias = bo directly)
    {
        dim3 grid(2, 148);    // 296 CTAs, exactly 2/SM
        hmma_gemm_kernel<1><<<grid, 256, SMEM_TOTAL_GEMM>>>(
            th, woT, bo, concat_p, out, ROWS);
    }
}